// round 1
// baseline (speedup 1.0000x reference)
#include <cuda_runtime.h>

#define BATCH 32
#define L 1024
#define HD 1024

// Scratch: raw affinity matrix A[b][q][dp] plus softmax stats.
__device__ float g_A[(size_t)BATCH * L * L];   // 128 MB
__device__ float g_rmax[BATCH * L];
__device__ float g_rinv[BATCH * L];
__device__ float g_cmax[BATCH * L];
__device__ float g_cinv[BATCH * L];

// ---------------------------------------------------------------------------
// K1: A[b] = q[b] @ d[b]^T   (NT GEMM, 1024x1024x1024 per batch)
// C[i,j] = sum_h Q[i,h] * D[j,h]
// ---------------------------------------------------------------------------
__global__ __launch_bounds__(256) void k_gemm_nt(const float* __restrict__ Q,
                                                 const float* __restrict__ D)
{
    int b = blockIdx.z;
    const float* Ap = Q + (size_t)b * L * HD;
    const float* Bp = D + (size_t)b * L * HD;
    float* Cp = g_A + (size_t)b * L * L;

    __shared__ float As[16][128];
    __shared__ float Bs[16][128];

    int tid = threadIdx.x;
    int tx = tid & 15, ty = tid >> 4;
    int row0 = blockIdx.y * 128, col0 = blockIdx.x * 128;
    int lr = tid >> 2, lc = (tid & 3) * 4;   // transpose-load mapping

    float acc[8][8] = {};

    for (int k0 = 0; k0 < HD; k0 += 16) {
        float4 a0 = *(const float4*)(Ap + (size_t)(row0 + lr) * HD + k0 + lc);
        float4 a1 = *(const float4*)(Ap + (size_t)(row0 + lr + 64) * HD + k0 + lc);
        float4 b0 = *(const float4*)(Bp + (size_t)(col0 + lr) * HD + k0 + lc);
        float4 b1 = *(const float4*)(Bp + (size_t)(col0 + lr + 64) * HD + k0 + lc);
        __syncthreads();
        As[lc + 0][lr] = a0.x; As[lc + 1][lr] = a0.y; As[lc + 2][lr] = a0.z; As[lc + 3][lr] = a0.w;
        As[lc + 0][lr + 64] = a1.x; As[lc + 1][lr + 64] = a1.y; As[lc + 2][lr + 64] = a1.z; As[lc + 3][lr + 64] = a1.w;
        Bs[lc + 0][lr] = b0.x; Bs[lc + 1][lr] = b0.y; Bs[lc + 2][lr] = b0.z; Bs[lc + 3][lr] = b0.w;
        Bs[lc + 0][lr + 64] = b1.x; Bs[lc + 1][lr + 64] = b1.y; Bs[lc + 2][lr + 64] = b1.z; Bs[lc + 3][lr + 64] = b1.w;
        __syncthreads();
        #pragma unroll
        for (int kk = 0; kk < 16; kk++) {
            float4 ar0 = *(const float4*)&As[kk][ty * 8];
            float4 ar1 = *(const float4*)&As[kk][ty * 8 + 4];
            float4 br0 = *(const float4*)&Bs[kk][tx * 8];
            float4 br1 = *(const float4*)&Bs[kk][tx * 8 + 4];
            float ar[8] = {ar0.x, ar0.y, ar0.z, ar0.w, ar1.x, ar1.y, ar1.z, ar1.w};
            float br[8] = {br0.x, br0.y, br0.z, br0.w, br1.x, br1.y, br1.z, br1.w};
            #pragma unroll
            for (int i = 0; i < 8; i++)
                #pragma unroll
                for (int j = 0; j < 8; j++)
                    acc[i][j] = fmaf(ar[i], br[j], acc[i][j]);
        }
    }
    #pragma unroll
    for (int i = 0; i < 8; i++) {
        float* crow = Cp + (size_t)(row0 + ty * 8 + i) * L + col0 + tx * 8;
        *(float4*)crow       = make_float4(acc[i][0], acc[i][1], acc[i][2], acc[i][3]);
        *(float4*)(crow + 4) = make_float4(acc[i][4], acc[i][5], acc[i][6], acc[i][7]);
    }
}

// ---------------------------------------------------------------------------
// K2a: per-row (over dp < d_len) online max / sum-of-exp
// ---------------------------------------------------------------------------
__global__ __launch_bounds__(256) void k_row_stats(const int* __restrict__ dlen)
{
    int b = blockIdx.y, row = blockIdx.x;
    int kl = dlen[b];
    const float* Ar = g_A + (size_t)b * L * L + (size_t)row * L;
    int tid = threadIdx.x;

    float m = -3.0e38f, s = 0.f;
    for (int j = tid; j < kl; j += 256) {
        float v = Ar[j];
        float nm = fmaxf(m, v);
        s = s * __expf(m - nm) + __expf(v - nm);
        m = nm;
    }
    #pragma unroll
    for (int off = 16; off; off >>= 1) {
        float om = __shfl_xor_sync(0xffffffffu, m, off);
        float os = __shfl_xor_sync(0xffffffffu, s, off);
        float nm = fmaxf(m, om);
        s = s * __expf(m - nm) + os * __expf(om - nm);
        m = nm;
    }
    __shared__ float sm[8], ss[8];
    int w = tid >> 5;
    if ((tid & 31) == 0) { sm[w] = m; ss[w] = s; }
    __syncthreads();
    if (tid == 0) {
        m = sm[0]; s = ss[0];
        #pragma unroll
        for (int i = 1; i < 8; i++) {
            float nm = fmaxf(m, sm[i]);
            s = s * __expf(m - nm) + ss[i] * __expf(sm[i] - nm);
            m = nm;
        }
        g_rmax[b * L + row] = m;
        g_rinv[b * L + row] = 1.f / s;
    }
}

// ---------------------------------------------------------------------------
// K2b: per-column (over q < q_len) online max / sum-of-exp
// ---------------------------------------------------------------------------
__global__ __launch_bounds__(256) void k_col_stats(const int* __restrict__ qlen)
{
    int b = blockIdx.y;
    int col = blockIdx.x * 256 + threadIdx.x;
    int kl = qlen[b];
    const float* Ab = g_A + (size_t)b * L * L;
    float m = -3.0e38f, s = 0.f;
    for (int q = 0; q < kl; q++) {
        float v = Ab[(size_t)q * L + col];
        float nm = fmaxf(m, v);
        s = s * __expf(m - nm) + __expf(v - nm);
        m = nm;
    }
    g_cmax[b * L + col] = m;
    g_cinv[b * L + col] = 1.f / s;
}

// ---------------------------------------------------------------------------
// K3: sq^T[b,q,h] = sum_{dp<d_len} exp(A[q,dp]-rmax[q])*rinv[q] * D[b,dp,h]
// Row-normalized weights applied during A-tile load (transpose-on-load).
// ---------------------------------------------------------------------------
__global__ __launch_bounds__(256) void k_rowsoft_gemm(const float* __restrict__ D,
                                                      const int* __restrict__ dlen,
                                                      float* __restrict__ Out)
{
    int b = blockIdx.z;
    const float* Ap = g_A + (size_t)b * L * L;   // [q, dp]
    const float* Bp = D + (size_t)b * L * HD;    // [dp, h]
    float* Cp = Out + (size_t)b * L * HD;        // [q, h]
    int kl = dlen[b];

    __shared__ float Ws[16][128];
    __shared__ float Bs[16][128];

    int tid = threadIdx.x;
    int tx = tid & 15, ty = tid >> 4;
    int row0 = blockIdx.y * 128, col0 = blockIdx.x * 128;
    int lr = tid >> 2, lc = (tid & 3) * 4;     // A transpose-load
    int ldr = tid >> 4, ldc = (tid & 15) * 4;  // B direct load

    float rm0 = g_rmax[b * L + row0 + lr],      ri0 = g_rinv[b * L + row0 + lr];
    float rm1 = g_rmax[b * L + row0 + lr + 64], ri1 = g_rinv[b * L + row0 + lr + 64];

    float acc[8][8] = {};
    int ktiles = (kl + 15) >> 4;

    for (int t = 0; t < ktiles; t++) {
        int k0 = t * 16;
        float4 a0 = *(const float4*)(Ap + (size_t)(row0 + lr) * L + k0 + lc);
        float4 a1 = *(const float4*)(Ap + (size_t)(row0 + lr + 64) * L + k0 + lc);
        float4 b0 = *(const float4*)(Bp + (size_t)(k0 + ldr) * HD + col0 + ldc);
        float4 b1 = *(const float4*)(Bp + (size_t)(k0 + ldr) * HD + col0 + ldc + 64);
        float w0x = (k0 + lc + 0 < kl) ? __expf(a0.x - rm0) * ri0 : 0.f;
        float w0y = (k0 + lc + 1 < kl) ? __expf(a0.y - rm0) * ri0 : 0.f;
        float w0z = (k0 + lc + 2 < kl) ? __expf(a0.z - rm0) * ri0 : 0.f;
        float w0w = (k0 + lc + 3 < kl) ? __expf(a0.w - rm0) * ri0 : 0.f;
        float w1x = (k0 + lc + 0 < kl) ? __expf(a1.x - rm1) * ri1 : 0.f;
        float w1y = (k0 + lc + 1 < kl) ? __expf(a1.y - rm1) * ri1 : 0.f;
        float w1z = (k0 + lc + 2 < kl) ? __expf(a1.z - rm1) * ri1 : 0.f;
        float w1w = (k0 + lc + 3 < kl) ? __expf(a1.w - rm1) * ri1 : 0.f;
        __syncthreads();
        Ws[lc + 0][lr] = w0x; Ws[lc + 1][lr] = w0y; Ws[lc + 2][lr] = w0z; Ws[lc + 3][lr] = w0w;
        Ws[lc + 0][lr + 64] = w1x; Ws[lc + 1][lr + 64] = w1y; Ws[lc + 2][lr + 64] = w1z; Ws[lc + 3][lr + 64] = w1w;
        *(float4*)&Bs[ldr][ldc] = b0;
        *(float4*)&Bs[ldr][ldc + 64] = b1;
        __syncthreads();
        #pragma unroll
        for (int kk = 0; kk < 16; kk++) {
            float4 ar0 = *(const float4*)&Ws[kk][ty * 8];
            float4 ar1 = *(const float4*)&Ws[kk][ty * 8 + 4];
            float4 br0 = *(const float4*)&Bs[kk][tx * 8];
            float4 br1 = *(const float4*)&Bs[kk][tx * 8 + 4];
            float ar[8] = {ar0.x, ar0.y, ar0.z, ar0.w, ar1.x, ar1.y, ar1.z, ar1.w};
            float br[8] = {br0.x, br0.y, br0.z, br0.w, br1.x, br1.y, br1.z, br1.w};
            #pragma unroll
            for (int i = 0; i < 8; i++)
                #pragma unroll
                for (int j = 0; j < 8; j++)
                    acc[i][j] = fmaf(ar[i], br[j], acc[i][j]);
        }
    }
    #pragma unroll
    for (int i = 0; i < 8; i++) {
        float* crow = Cp + (size_t)(row0 + ty * 8 + i) * HD + col0 + tx * 8;
        *(float4*)crow       = make_float4(acc[i][0], acc[i][1], acc[i][2], acc[i][3]);
        *(float4*)(crow + 4) = make_float4(acc[i][4], acc[i][5], acc[i][6], acc[i][7]);
    }
}

// ---------------------------------------------------------------------------
// K4/K5: Out[b,dp,h] = sum_{q<q_len} exp(A[q,dp]-cmax[dp])*cinv[dp] * Bsrc[b,q,h]
// Column-normalized weights; A read in natural layout (K-major rows), no transpose.
// K4: Bsrc = q   -> sd^T.   K5: Bsrc = sq^T -> cd^T.
// ---------------------------------------------------------------------------
__global__ __launch_bounds__(256) void k_colsoft_gemm(const float* __restrict__ Bsrc,
                                                      const int* __restrict__ qlen,
                                                      float* __restrict__ Out)
{
    int b = blockIdx.z;
    const float* Ap = g_A + (size_t)b * L * L;     // [q, dp]
    const float* Bp = Bsrc + (size_t)b * L * HD;   // [q, h]
    float* Cp = Out + (size_t)b * L * HD;          // [dp, h]
    int kl = qlen[b];

    __shared__ float Ws[16][128];
    __shared__ float Bs[16][128];
    __shared__ float scm[128], sci[128];

    int tid = threadIdx.x;
    int tx = tid & 15, ty = tid >> 4;
    int m0 = blockIdx.y * 128, col0 = blockIdx.x * 128;
    int ldr = tid >> 4, ldc = (tid & 15) * 4;   // B direct load
    int ka = tid >> 5, mc = (tid & 31) * 4;     // A direct load (16x128)

    if (tid < 128) {
        scm[tid] = g_cmax[b * L + m0 + tid];
        sci[tid] = g_cinv[b * L + m0 + tid];
    }
    __syncthreads();

    float acc[8][8] = {};
    int ktiles = (kl + 15) >> 4;

    for (int t = 0; t < ktiles; t++) {
        int k0 = t * 16;
        float4 a0 = *(const float4*)(Ap + (size_t)(k0 + ka) * L + m0 + mc);
        float4 a1 = *(const float4*)(Ap + (size_t)(k0 + ka + 8) * L + m0 + mc);
        float4 b0 = *(const float4*)(Bp + (size_t)(k0 + ldr) * HD + col0 + ldc);
        float4 b1 = *(const float4*)(Bp + (size_t)(k0 + ldr) * HD + col0 + ldc + 64);
        bool v0 = (k0 + ka) < kl, v1 = (k0 + ka + 8) < kl;
        float w0x = v0 ? __expf(a0.x - scm[mc + 0]) * sci[mc + 0] : 0.f;
        float w0y = v0 ? __expf(a0.y - scm[mc + 1]) * sci[mc + 1] : 0.f;
        float w0z = v0 ? __expf(a0.z - scm[mc + 2]) * sci[mc + 2] : 0.f;
        float w0w = v0 ? __expf(a0.w - scm[mc + 3]) * sci[mc + 3] : 0.f;
        float w1x = v1 ? __expf(a1.x - scm[mc + 0]) * sci[mc + 0] : 0.f;
        float w1y = v1 ? __expf(a1.y - scm[mc + 1]) * sci[mc + 1] : 0.f;
        float w1z = v1 ? __expf(a1.z - scm[mc + 2]) * sci[mc + 2] : 0.f;
        float w1w = v1 ? __expf(a1.w - scm[mc + 3]) * sci[mc + 3] : 0.f;
        __syncthreads();
        *(float4*)&Ws[ka][mc]     = make_float4(w0x, w0y, w0z, w0w);
        *(float4*)&Ws[ka + 8][mc] = make_float4(w1x, w1y, w1z, w1w);
        *(float4*)&Bs[ldr][ldc]      = b0;
        *(float4*)&Bs[ldr][ldc + 64] = b1;
        __syncthreads();
        #pragma unroll
        for (int kk = 0; kk < 16; kk++) {
            float4 ar0 = *(const float4*)&Ws[kk][ty * 8];
            float4 ar1 = *(const float4*)&Ws[kk][ty * 8 + 4];
            float4 br0 = *(const float4*)&Bs[kk][tx * 8];
            float4 br1 = *(const float4*)&Bs[kk][tx * 8 + 4];
            float ar[8] = {ar0.x, ar0.y, ar0.z, ar0.w, ar1.x, ar1.y, ar1.z, ar1.w};
            float br[8] = {br0.x, br0.y, br0.z, br0.w, br1.x, br1.y, br1.z, br1.w};
            #pragma unroll
            for (int i = 0; i < 8; i++)
                #pragma unroll
                for (int j = 0; j < 8; j++)
                    acc[i][j] = fmaf(ar[i], br[j], acc[i][j]);
        }
    }
    #pragma unroll
    for (int i = 0; i < 8; i++) {
        float* crow = Cp + (size_t)(m0 + ty * 8 + i) * HD + col0 + tx * 8;
        *(float4*)crow       = make_float4(acc[i][0], acc[i][1], acc[i][2], acc[i][3]);
        *(float4*)(crow + 4) = make_float4(acc[i][4], acc[i][5], acc[i][6], acc[i][7]);
    }
}

// ---------------------------------------------------------------------------
extern "C" void kernel_launch(void* const* d_in, const int* in_sizes, int n_in,
                              void* d_out, int out_size)
{
    const float* q    = (const float*)d_in[0];   // [B, Lq, H]
    const float* dmat = (const float*)d_in[1];   // [B, Ld, H]
    const int*   qlen = (const int*)d_in[2];     // [B]
    const int*   dlen = (const int*)d_in[3];     // [B]

    float* out = (float*)d_out;
    const size_t ten = (size_t)BATCH * L * HD;   // one output tensor's elements
    float* out_cd = out;              // cd^T  [B, Ld, H]
    float* out_sq = out + ten;        // sq^T  [B, Lq, H]
    float* out_sd = out + 2 * ten;    // sd^T  [B, Ld, H]

    dim3 gemm_grid(HD / 128, L / 128, BATCH);   // (n-tiles, m-tiles, batch)

    // 1) A = q @ d^T
    k_gemm_nt<<<dim3(L / 128, L / 128, BATCH), 256>>>(q, dmat);
    // 2) softmax statistics of A
    k_row_stats<<<dim3(L, BATCH), 256>>>(dlen);
    k_col_stats<<<dim3(L / 256, BATCH), 256>>>(qlen);
    // 3) sq^T = ad^T @ d      (row-normalized weights)
    k_rowsoft_gemm<<<gemm_grid, 256>>>(dmat, dlen, out_sq);
    // 4) sd^T = aq^T @ q      (col-normalized weights)
    k_colsoft_gemm<<<gemm_grid, 256>>>(q, qlen, out_sd);
    // 5) cd^T = aq^T @ sq^T
    k_colsoft_gemm<<<gemm_grid, 256>>>(out_sq, qlen, out_cd);
}

// round 4
// speedup vs baseline: 2.5560x; 2.5560x over previous
#include <cuda_runtime.h>
#include <cuda_bf16.h>
#include <cstdint>

#define BATCH 32
#define L 1024
#define HD 1024

// ---------------------------------------------------------------------------
// Scratch (__device__ globals; no runtime allocation)
// ---------------------------------------------------------------------------
__device__ float g_A[(size_t)BATCH * L * L];   // raw logits, 128 MB
__device__ float g_rmax[BATCH * L];
__device__ float g_rinv[BATCH * L];
__device__ float g_cmax[BATCH * L];
__device__ float g_cinv[BATCH * L];

#define NEL ((size_t)BATCH * L * HD)
__device__ __nv_bfloat16 g_q0[NEL], g_q1[NEL], g_q2[NEL];   // q 3-way split (natural)
__device__ __nv_bfloat16 g_d0[NEL], g_d1[NEL], g_d2[NEL];   // d 3-way split (natural)
__device__ __nv_bfloat16 g_dT0[NEL], g_dT1[NEL];            // d^T 2-way split
__device__ __nv_bfloat16 g_qT0[NEL], g_qT1[NEL];            // q^T 2-way split
__device__ __nv_bfloat16 g_sT0[NEL], g_sT1[NEL];            // sq^T 2-way split
__device__ __nv_bfloat16 g_wr0[NEL], g_wr1[NEL];            // row-softmax weights [q][dp]
__device__ __nv_bfloat16 g_wc0[NEL], g_wc1[NEL];            // col-softmax weights [dp][q]

// ---------------------------------------------------------------------------
// Helpers
// ---------------------------------------------------------------------------
__device__ __forceinline__ uint32_t smem_u32(const void* p) {
    uint32_t a;
    asm("{ .reg .u64 t; cvta.to.shared.u64 t, %1; cvt.u32.u64 %0, t; }" : "=r"(a) : "l"(p));
    return a;
}

#define LDSM4(R0, R1, R2, R3, addr)                                             \
    asm volatile("ldmatrix.sync.aligned.m8n8.x4.shared.b16 {%0,%1,%2,%3}, [%4];" \
                 : "=r"(R0), "=r"(R1), "=r"(R2), "=r"(R3) : "r"(addr))

#define CP_ASYNC16(saddr, gaddr) \
    asm volatile("cp.async.cg.shared.global [%0], [%1], 16;" :: "r"(saddr), "l"(gaddr))
#define CP_COMMIT() asm volatile("cp.async.commit_group;" ::: "memory")
#define CP_WAIT1()  asm volatile("cp.async.wait_group 1;" ::: "memory")

__device__ __forceinline__ void mma16816(float& c0, float& c1, float& c2, float& c3,
                                         uint32_t a0, uint32_t a1, uint32_t a2, uint32_t a3,
                                         uint32_t b0, uint32_t b1) {
    asm volatile(
        "mma.sync.aligned.m16n8k16.row.col.f32.bf16.bf16.f32 "
        "{%0,%1,%2,%3}, {%4,%5,%6,%7}, {%8,%9}, {%0,%1,%2,%3};"
        : "+f"(c0), "+f"(c1), "+f"(c2), "+f"(c3)
        : "r"(a0), "r"(a1), "r"(a2), "r"(a3), "r"(b0), "r"(b1));
}

__device__ __forceinline__ void split2f(float x, __nv_bfloat16& a, __nv_bfloat16& b) {
    a = __float2bfloat16(x);
    b = __float2bfloat16(x - __bfloat162float(a));
}
__device__ __forceinline__ void split3f(float x, __nv_bfloat16& a, __nv_bfloat16& b,
                                        __nv_bfloat16& c) {
    a = __float2bfloat16(x);
    float r = x - __bfloat162float(a);
    b = __float2bfloat16(r);
    c = __float2bfloat16(r - __bfloat162float(b));
}

// ---------------------------------------------------------------------------
// Conversion kernels
// ---------------------------------------------------------------------------
union BU4 { __nv_bfloat16 h[4]; uint2 u; };

__global__ __launch_bounds__(256) void k_split3(const float4* __restrict__ x,
                                                uint2* __restrict__ o0,
                                                uint2* __restrict__ o1,
                                                uint2* __restrict__ o2) {
    size_t i = (size_t)blockIdx.x * 256 + threadIdx.x;
    float4 v = x[i];
    float xs[4] = {v.x, v.y, v.z, v.w};
    BU4 p0, p1, p2;
    #pragma unroll
    for (int c = 0; c < 4; c++) split3f(xs[c], p0.h[c], p1.h[c], p2.h[c]);
    o0[i] = p0.u; o1[i] = p1.u; o2[i] = p2.u;
}

// Transpose + 2-way split: out[c][r] = split(in[r][c]) per batch
__global__ void k_splitT2(const float* __restrict__ x,
                          __nv_bfloat16* __restrict__ o0,
                          __nv_bfloat16* __restrict__ o1) {
    __shared__ float tl[32][33];
    int tx = threadIdx.x, ty = threadIdx.y, b = blockIdx.z;
    size_t boff = (size_t)b << 20;
    int r0 = blockIdx.y * 32, c0 = blockIdx.x * 32;
    #pragma unroll
    for (int j = 0; j < 4; j++)
        tl[ty + j * 8][tx] = x[boff + (size_t)(r0 + ty + j * 8) * L + c0 + tx];
    __syncthreads();
    #pragma unroll
    for (int j = 0; j < 4; j++) {
        int orow = c0 + ty + j * 8, ocol = r0 + tx;
        float v = tl[tx][ty + j * 8];
        __nv_bfloat16 h0, h1;
        split2f(v, h0, h1);
        size_t oi = boff + (size_t)orow * L + ocol;
        o0[oi] = h0; o1[oi] = h1;
    }
}

// Row-softmax weights (natural layout): wr[q][dp] = exp(A-rmax)*rinv, 0 beyond dlen
__global__ __launch_bounds__(256) void k_wr_split(const int* __restrict__ dlen) {
    int b = blockIdx.y, q = blockIdx.x, tid = threadIdx.x;
    int kl = dlen[b];
    float rm = g_rmax[b * L + q], ri = g_rinv[b * L + q];
    size_t base = ((size_t)b << 20) + ((size_t)q << 10);
    float4 v = *(const float4*)(g_A + base + tid * 4);
    float xs[4] = {v.x, v.y, v.z, v.w};
    BU4 p0, p1;
    #pragma unroll
    for (int c = 0; c < 4; c++) {
        int dp = tid * 4 + c;
        float w = (dp < kl) ? __expf(xs[c] - rm) * ri : 0.f;
        split2f(w, p0.h[c], p1.h[c]);
    }
    size_t oi = (base >> 2) + tid;
    ((uint2*)g_wr0)[oi] = p0.u;
    ((uint2*)g_wr1)[oi] = p1.u;
}

// Col-softmax weights, transposed: wc[dp][q] = exp(A[q][dp]-cmax[dp])*cinv[dp]
__global__ void k_wc_splitT(const int* __restrict__ qlen) {
    __shared__ float tl[32][33];
    int tx = threadIdx.x, ty = threadIdx.y, b = blockIdx.z;
    int kl = qlen[b];
    size_t boff = (size_t)b << 20;
    int r0 = blockIdx.y * 32, c0 = blockIdx.x * 32;   // r = q, c = dp
    #pragma unroll
    for (int j = 0; j < 4; j++)
        tl[ty + j * 8][tx] = g_A[boff + (size_t)(r0 + ty + j * 8) * L + c0 + tx];
    __syncthreads();
    #pragma unroll
    for (int j = 0; j < 4; j++) {
        int dp = c0 + ty + j * 8, qq = r0 + tx;
        float v = tl[tx][ty + j * 8];
        float w = (qq < kl) ? __expf(v - g_cmax[b * L + dp]) * g_cinv[b * L + dp] : 0.f;
        __nv_bfloat16 h0, h1;
        split2f(w, h0, h1);
        size_t oi = boff + (size_t)dp * L + qq;
        g_wc0[oi] = h0; g_wc1[oi] = h1;
    }
}

// ---------------------------------------------------------------------------
// Softmax statistics (operate on g_A)
// ---------------------------------------------------------------------------
__global__ __launch_bounds__(256) void k_row_stats(const int* __restrict__ dlen) {
    int b = blockIdx.y, row = blockIdx.x;
    int kl = dlen[b];
    const float* Ar = g_A + (size_t)b * L * L + (size_t)row * L;
    int tid = threadIdx.x;
    float m = -3.0e38f, s = 0.f;
    for (int j = tid; j < kl; j += 256) {
        float v = Ar[j];
        float nm = fmaxf(m, v);
        s = s * __expf(m - nm) + __expf(v - nm);
        m = nm;
    }
    #pragma unroll
    for (int off = 16; off; off >>= 1) {
        float om = __shfl_xor_sync(0xffffffffu, m, off);
        float os = __shfl_xor_sync(0xffffffffu, s, off);
        float nm = fmaxf(m, om);
        s = s * __expf(m - nm) + os * __expf(om - nm);
        m = nm;
    }
    __shared__ float sm[8], ss[8];
    int w = tid >> 5;
    if ((tid & 31) == 0) { sm[w] = m; ss[w] = s; }
    __syncthreads();
    if (tid == 0) {
        m = sm[0]; s = ss[0];
        #pragma unroll
        for (int i = 1; i < 8; i++) {
            float nm = fmaxf(m, sm[i]);
            s = s * __expf(m - nm) + ss[i] * __expf(sm[i] - nm);
            m = nm;
        }
        g_rmax[b * L + row] = m;
        g_rinv[b * L + row] = 1.f / s;
    }
}

__global__ __launch_bounds__(256) void k_col_stats(const int* __restrict__ qlen) {
    int b = blockIdx.y;
    int col = blockIdx.x * 256 + threadIdx.x;
    int kl = qlen[b];
    const float* Ab = g_A + (size_t)b * L * L;
    float m = -3.0e38f, s = 0.f;
    for (int q = 0; q < kl; q++) {
        float v = Ab[(size_t)q * L + col];
        float nm = fmaxf(m, v);
        s = s * __expf(m - nm) + __expf(v - nm);
        m = nm;
    }
    g_cmax[b * L + col] = m;
    g_cinv[b * L + col] = 1.f / s;
}

// ---------------------------------------------------------------------------
// Split-bf16 HMMA GEMM (mma.sync m16n8k16, portable PTX path)
// Out[m][n] = sum_k A(m,k) * B(n,k); A,B each split into NT bf16 terms;
// NP product-term combinations accumulated into one fp32 accumulator.
// Block tile 128x128, warp tile 64x32 (2x4 warps), Kc=32, cp.async x2 buffer.
// ---------------------------------------------------------------------------
#define TILE_B 10240                       // 128 rows * 80B (64B data + 16B pad)

template <int NT, int NP>
__global__ __launch_bounds__(256, 1) void k_mma_bf16(
    const __nv_bfloat16* __restrict__ A0, const __nv_bfloat16* __restrict__ A1,
    const __nv_bfloat16* __restrict__ A2,
    const __nv_bfloat16* __restrict__ B0, const __nv_bfloat16* __restrict__ B1,
    const __nv_bfloat16* __restrict__ B2,
    const int* klen_arr, int klen_fixed, float* __restrict__ Out) {
    extern __shared__ char smem[];
    const uint32_t sbase = smem_u32(smem);
    constexpr int STAGE = 2 * NT * TILE_B;

    const int tid = threadIdx.x, lane = tid & 31, wid = tid >> 5;
    const int b = blockIdx.z, m0 = blockIdx.y * 128, n0 = blockIdx.x * 128;
    const int kl = klen_arr ? klen_arr[b] : klen_fixed;
    const int ktiles = (kl + 31) >> 5;

    const size_t boff = (size_t)b << 20;
    const __nv_bfloat16* gp[2 * NT];
    gp[0] = A0 + boff + (size_t)m0 * L;
    gp[1] = A1 + boff + (size_t)m0 * L;
    if (NT == 3) gp[2] = A2 + boff + (size_t)m0 * L;
    gp[NT + 0] = B0 + boff + (size_t)n0 * L;
    gp[NT + 1] = B1 + boff + (size_t)n0 * L;
    if (NT == 3) gp[NT + 2] = B2 + boff + (size_t)n0 * L;

    // product-term tables (compile-time under unroll)
    constexpr int PA6[6] = {0, 0, 1, 1, 0, 2}, PB6[6] = {0, 1, 0, 1, 2, 0};
    constexpr int PA3[3] = {0, 0, 1},          PB3[3] = {0, 1, 0};

    // warp layout: 2 (m) x 4 (n)
    const int warp_m = (wid >> 2) * 64;
    const int warp_n = (wid & 3) * 32;
    // ldmatrix per-thread base addressing
    const int rowA = warp_m + (lane & 7) + ((lane >> 3) & 1) * 8;
    const int chA = (lane >> 4) & 1;
    const int rowB = warp_n + (lane & 7) + ((lane >> 4) & 1) * 8;
    const int chB = (lane >> 3) & 1;

    float acc[4][4][4] = {};   // [m-frag][n-frag][mma reg]

    // ---- stage loader (cp.async, 16B per thread op) ----
    auto load_stage = [&](int t, int buf) {
        const int k0 = t * 32;
        const uint32_t sb = sbase + buf * STAGE;
        #pragma unroll
        for (int tile = 0; tile < 2 * NT; tile++)
            #pragma unroll
            for (int pp = 0; pp < 2; pp++) {
                int id = tid + pp * 256;
                int row = id >> 2, ch = id & 3;
                uint32_t sa = sb + tile * TILE_B + row * 80 + ch * 16;
                const __nv_bfloat16* ga = gp[tile] + (size_t)row * L + k0 + ch * 8;
                CP_ASYNC16(sa, ga);
            }
    };

    load_stage(0, 0);
    CP_COMMIT();

    for (int t = 0; t < ktiles; t++) {
        if (t + 1 < ktiles) load_stage(t + 1, (t + 1) & 1);
        CP_COMMIT();
        CP_WAIT1();
        __syncthreads();

        const uint32_t sb = sbase + (t & 1) * STAGE;
        #pragma unroll
        for (int ks = 0; ks < 2; ks++) {
            // cache B fragments for all NT terms: Bf[term][8]
            uint32_t Bf[NT][8];
            #pragma unroll
            for (int tm = 0; tm < NT; tm++)
                #pragma unroll
                for (int g2 = 0; g2 < 2; g2++) {
                    uint32_t a = sb + (NT + tm) * TILE_B + (rowB + g2 * 16) * 80
                               + (chB + 2 * ks) * 16;
                    LDSM4(Bf[tm][g2 * 4 + 0], Bf[tm][g2 * 4 + 1],
                          Bf[tm][g2 * 4 + 2], Bf[tm][g2 * 4 + 3], a);
                }
            uint32_t Af[16];
            #pragma unroll
            for (int p = 0; p < NP; p++) {
                const int pa = (NP == 6) ? PA6[p] : PA3[p];
                const int pb = (NP == 6) ? PB6[p] : PB3[p];
                const int pap = (p == 0) ? -1 : ((NP == 6) ? PA6[p - 1] : PA3[p - 1]);
                if (pa != pap) {
                    #pragma unroll
                    for (int f = 0; f < 4; f++) {
                        uint32_t a = sb + pa * TILE_B + (rowA + f * 16) * 80
                                   + (chA + 2 * ks) * 16;
                        LDSM4(Af[f * 4 + 0], Af[f * 4 + 1], Af[f * 4 + 2], Af[f * 4 + 3], a);
                    }
                }
                #pragma unroll
                for (int f = 0; f < 4; f++)
                    #pragma unroll
                    for (int g = 0; g < 4; g++) {
                        uint32_t b0 = Bf[pb][(g >> 1) * 4 + (g & 1) * 2];
                        uint32_t b1 = Bf[pb][(g >> 1) * 4 + (g & 1) * 2 + 1];
                        mma16816(acc[f][g][0], acc[f][g][1], acc[f][g][2], acc[f][g][3],
                                 Af[f * 4], Af[f * 4 + 1], Af[f * 4 + 2], Af[f * 4 + 3],
                                 b0, b1);
                    }
            }
        }
        __syncthreads();
    }

    // ---- epilogue: write fp32 results ----
    float* Ob = Out + boff;
    #pragma unroll
    for (int f = 0; f < 4; f++)
        #pragma unroll
        for (int g = 0; g < 4; g++) {
            int row = m0 + warp_m + f * 16 + (lane >> 2);
            int col = n0 + warp_n + g * 8 + (lane & 3) * 2;
            *(float2*)(Ob + (size_t)row * L + col) = make_float2(acc[f][g][0], acc[f][g][1]);
            *(float2*)(Ob + (size_t)(row + 8) * L + col) = make_float2(acc[f][g][2], acc[f][g][3]);
        }
}

// ---------------------------------------------------------------------------
extern "C" void kernel_launch(void* const* d_in, const int* in_sizes, int n_in,
                              void* d_out, int out_size) {
    const float* q = (const float*)d_in[0];
    const float* dmat = (const float*)d_in[1];
    const int* qlen = (const int*)d_in[2];
    const int* dlen = (const int*)d_in[3];

    float* out = (float*)d_out;
    const size_t ten = (size_t)BATCH * L * HD;
    float* out_cd = out;
    float* out_sq = out + ten;
    float* out_sd = out + 2 * ten;

    void *pA, *pq0, *pq1, *pq2, *pd0, *pd1, *pd2;
    void *pdT0, *pdT1, *pqT0, *pqT1, *psT0, *psT1, *pwr0, *pwr1, *pwc0, *pwc1;
    cudaGetSymbolAddress(&pA, g_A);
    cudaGetSymbolAddress(&pq0, g_q0); cudaGetSymbolAddress(&pq1, g_q1); cudaGetSymbolAddress(&pq2, g_q2);
    cudaGetSymbolAddress(&pd0, g_d0); cudaGetSymbolAddress(&pd1, g_d1); cudaGetSymbolAddress(&pd2, g_d2);
    cudaGetSymbolAddress(&pdT0, g_dT0); cudaGetSymbolAddress(&pdT1, g_dT1);
    cudaGetSymbolAddress(&pqT0, g_qT0); cudaGetSymbolAddress(&pqT1, g_qT1);
    cudaGetSymbolAddress(&psT0, g_sT0); cudaGetSymbolAddress(&psT1, g_sT1);
    cudaGetSymbolAddress(&pwr0, g_wr0); cudaGetSymbolAddress(&pwr1, g_wr1);
    cudaGetSymbolAddress(&pwc0, g_wc0); cudaGetSymbolAddress(&pwc1, g_wc1);

    const int SMEM6 = 2 * 6 * TILE_B;   // 122880 (NT=3)
    const int SMEM4 = 2 * 4 * TILE_B;   // 81920  (NT=2)
    cudaFuncSetAttribute(k_mma_bf16<3, 6>, cudaFuncAttributeMaxDynamicSharedMemorySize, SMEM6);
    cudaFuncSetAttribute(k_mma_bf16<2, 3>, cudaFuncAttributeMaxDynamicSharedMemorySize, SMEM4);

    dim3 gg(HD / 128, L / 128, BATCH);
    dim3 tg(32, 32, 32), tb(32, 8);
    int nsplit = (int)(NEL / 4 / 256);

    // 1) 3-way splits of inputs
    k_split3<<<nsplit, 256>>>((const float4*)q, (uint2*)pq0, (uint2*)pq1, (uint2*)pq2);
    k_split3<<<nsplit, 256>>>((const float4*)dmat, (uint2*)pd0, (uint2*)pd1, (uint2*)pd2);

    // 2) K1: A = q @ d^T  (fp32-accurate via 6 bf16 product terms)
    k_mma_bf16<3, 6><<<gg, 256, SMEM6>>>(
        (const __nv_bfloat16*)pq0, (const __nv_bfloat16*)pq1, (const __nv_bfloat16*)pq2,
        (const __nv_bfloat16*)pd0, (const __nv_bfloat16*)pd1, (const __nv_bfloat16*)pd2,
        nullptr, L, (float*)pA);

    // 3) softmax stats
    k_row_stats<<<dim3(L, BATCH), 256>>>(dlen);
    k_col_stats<<<dim3(L / 256, BATCH), 256>>>(qlen);

    // 4) K3: sq^T = Wr @ d^T
    k_wr_split<<<dim3(L, BATCH), 256>>>(dlen);
    k_splitT2<<<tg, tb>>>(dmat, (__nv_bfloat16*)pdT0, (__nv_bfloat16*)pdT1);
    k_mma_bf16<2, 3><<<gg, 256, SMEM4>>>(
        (const __nv_bfloat16*)pwr0, (const __nv_bfloat16*)pwr1, nullptr,
        (const __nv_bfloat16*)pdT0, (const __nv_bfloat16*)pdT1, nullptr,
        dlen, 0, out_sq);

    // 5) K4: sd^T = Wc @ q^T
    k_wc_splitT<<<tg, tb>>>(qlen);
    k_splitT2<<<tg, tb>>>(q, (__nv_bfloat16*)pqT0, (__nv_bfloat16*)pqT1);
    k_mma_bf16<2, 3><<<gg, 256, SMEM4>>>(
        (const __nv_bfloat16*)pwc0, (const __nv_bfloat16*)pwc1, nullptr,
        (const __nv_bfloat16*)pqT0, (const __nv_bfloat16*)pqT1, nullptr,
        qlen, 0, out_sd);

    // 6) K5: cd^T = Wc @ sq^T
    k_splitT2<<<tg, tb>>>(out_sq, (__nv_bfloat16*)psT0, (__nv_bfloat16*)psT1);
    k_mma_bf16<2, 3><<<gg, 256, SMEM4>>>(
        (const __nv_bfloat16*)pwc0, (const __nv_bfloat16*)pwc1, nullptr,
        (const __nv_bfloat16*)psT0, (const __nv_bfloat16*)psT1, nullptr,
        qlen, 0, out_cd);
}

// round 5
// speedup vs baseline: 4.7252x; 1.8487x over previous
#include <cuda_runtime.h>
#include <cuda_fp16.h>
#include <cstdint>

#define BATCH 32
#define L 1024
#define HD 1024

// ---------------------------------------------------------------------------
// Scratch (__device__ globals; no runtime allocation)
// ---------------------------------------------------------------------------
__device__ float g_A[(size_t)BATCH * L * L];   // raw logits, 128 MB
__device__ float g_rmax[BATCH * L];
__device__ float g_rinv[BATCH * L];
__device__ float g_cmax[BATCH * L];
__device__ float g_cinv[BATCH * L];

#define NEL ((size_t)BATCH * L * HD)
__device__ __half g_q0[NEL], g_q1[NEL];   // q 2-way fp16 split (natural)
__device__ __half g_d0[NEL], g_d1[NEL];   // d 2-way fp16 split (natural)
__device__ __half g_dT[NEL];              // d^T single fp16
__device__ __half g_qT[NEL];              // q^T single fp16
__device__ __half g_sT[NEL];              // sq^T single fp16
__device__ __half g_wr[NEL];              // row-softmax weights [q][dp], fp16
__device__ __half g_wc[NEL];              // col-softmax weights [dp][q], fp16

// ---------------------------------------------------------------------------
// Helpers
// ---------------------------------------------------------------------------
__device__ __forceinline__ uint32_t smem_u32(const void* p) {
    uint32_t a;
    asm("{ .reg .u64 t; cvta.to.shared.u64 t, %1; cvt.u32.u64 %0, t; }" : "=r"(a) : "l"(p));
    return a;
}

#define LDSM4(R0, R1, R2, R3, addr)                                             \
    asm volatile("ldmatrix.sync.aligned.m8n8.x4.shared.b16 {%0,%1,%2,%3}, [%4];" \
                 : "=r"(R0), "=r"(R1), "=r"(R2), "=r"(R3) : "r"(addr))

#define CP_ASYNC16(saddr, gaddr) \
    asm volatile("cp.async.cg.shared.global [%0], [%1], 16;" :: "r"(saddr), "l"(gaddr))
#define CP_COMMIT() asm volatile("cp.async.commit_group;" ::: "memory")
#define CP_WAIT1()  asm volatile("cp.async.wait_group 1;" ::: "memory")

__device__ __forceinline__ void mma16816(float& c0, float& c1, float& c2, float& c3,
                                         uint32_t a0, uint32_t a1, uint32_t a2, uint32_t a3,
                                         uint32_t b0, uint32_t b1) {
    asm volatile(
        "mma.sync.aligned.m16n8k16.row.col.f32.f16.f16.f32 "
        "{%0,%1,%2,%3}, {%4,%5,%6,%7}, {%8,%9}, {%0,%1,%2,%3};"
        : "+f"(c0), "+f"(c1), "+f"(c2), "+f"(c3)
        : "r"(a0), "r"(a1), "r"(a2), "r"(a3), "r"(b0), "r"(b1));
}

// ---------------------------------------------------------------------------
// Conversion kernels
// ---------------------------------------------------------------------------
union HU4 { __half h[4]; uint2 u; };

// fp32 -> 2-way fp16 split, natural layout
__global__ __launch_bounds__(256) void k_split2h(const float4* __restrict__ x,
                                                 uint2* __restrict__ o0,
                                                 uint2* __restrict__ o1) {
    size_t i = (size_t)blockIdx.x * 256 + threadIdx.x;
    float4 v = x[i];
    float xs[4] = {v.x, v.y, v.z, v.w};
    HU4 p0, p1;
    #pragma unroll
    for (int c = 0; c < 4; c++) {
        p0.h[c] = __float2half_rn(xs[c]);
        p1.h[c] = __float2half_rn(xs[c] - __half2float(p0.h[c]));
    }
    o0[i] = p0.u;
    o1[i] = p1.u;
}

// Per-batch transpose, single fp16: o[c][r] = half(x[r][c])
__global__ void k_splitT1h(const float* __restrict__ x, __half* __restrict__ o) {
    __shared__ float tl[32][33];
    int tx = threadIdx.x, ty = threadIdx.y, b = blockIdx.z;
    size_t boff = (size_t)b << 20;
    int r0 = blockIdx.y * 32, c0 = blockIdx.x * 32;
    #pragma unroll
    for (int j = 0; j < 4; j++)
        tl[ty + j * 8][tx] = x[boff + (size_t)(r0 + ty + j * 8) * L + c0 + tx];
    __syncthreads();
    #pragma unroll
    for (int j = 0; j < 4; j++) {
        int orow = c0 + ty + j * 8, ocol = r0 + tx;
        o[boff + (size_t)orow * L + ocol] = __float2half_rn(tl[tx][ty + j * 8]);
    }
}

// Fused weight generation: one read of A produces
//   wr[q][dp]  = exp(A - rmax[q]) * rinv[q]   (0 for dp >= dlen)   natural
//   wc[dp][q]  = exp(A - cmax[dp]) * cinv[dp] (0 for q  >= qlen)   transposed
__global__ void k_weights(const int* __restrict__ qlen, const int* __restrict__ dlen) {
    __shared__ float tl[32][33];
    int tx = threadIdx.x, ty = threadIdx.y, b = blockIdx.z;
    int klq = qlen[b], kld = dlen[b];
    size_t boff = (size_t)b << 20;
    int r0 = blockIdx.y * 32, c0 = blockIdx.x * 32;   // r = q, c = dp
    #pragma unroll
    for (int j = 0; j < 4; j++)
        tl[ty + j * 8][tx] = g_A[boff + (size_t)(r0 + ty + j * 8) * L + c0 + tx];
    __syncthreads();
    #pragma unroll
    for (int j = 0; j < 4; j++) {
        int qq = r0 + ty + j * 8, dp = c0 + tx;
        float v = tl[ty + j * 8][tx];
        float w = (dp < kld) ? __expf(v - g_rmax[b * L + qq]) * g_rinv[b * L + qq] : 0.f;
        g_wr[boff + (size_t)qq * L + dp] = __float2half_rn(w);
    }
    #pragma unroll
    for (int j = 0; j < 4; j++) {
        int dp = c0 + ty + j * 8, qq = r0 + tx;
        float v = tl[tx][ty + j * 8];
        float w = (qq < klq) ? __expf(v - g_cmax[b * L + dp]) * g_cinv[b * L + dp] : 0.f;
        g_wc[boff + (size_t)dp * L + qq] = __float2half_rn(w);
    }
}

// ---------------------------------------------------------------------------
// Softmax statistics
// ---------------------------------------------------------------------------
// warp-per-row: whole row resident in registers (8 x float4 per lane)
__global__ __launch_bounds__(256) void k_row_stats(const int* __restrict__ dlen) {
    int b = blockIdx.y;
    int row = blockIdx.x * 8 + (threadIdx.x >> 5);
    int lane = threadIdx.x & 31;
    int kl = dlen[b];
    const float4* Ar = (const float4*)(g_A + ((size_t)b << 20) + ((size_t)row << 10));
    float v[32];
    #pragma unroll
    for (int i = 0; i < 8; i++) {
        float4 t = Ar[lane + i * 32];
        v[i * 4 + 0] = t.x; v[i * 4 + 1] = t.y; v[i * 4 + 2] = t.z; v[i * 4 + 3] = t.w;
    }
    float m = -1e30f;
    #pragma unroll
    for (int i = 0; i < 8; i++)
        #pragma unroll
        for (int c = 0; c < 4; c++) {
            int idx = (lane + i * 32) * 4 + c;
            if (idx >= kl) v[i * 4 + c] = -1e30f;
            m = fmaxf(m, v[i * 4 + c]);
        }
    #pragma unroll
    for (int off = 16; off; off >>= 1) m = fmaxf(m, __shfl_xor_sync(~0u, m, off));
    float s = 0.f;
    #pragma unroll
    for (int i = 0; i < 32; i++) s += __expf(v[i] - m);
    #pragma unroll
    for (int off = 16; off; off >>= 1) s += __shfl_xor_sync(~0u, s, off);
    if (lane == 0) {
        g_rmax[b * L + row] = m;
        g_rinv[b * L + row] = 1.f / s;
    }
}

// column stats: 4 independent online chains -> MLP 4
__global__ __launch_bounds__(256) void k_col_stats(const int* __restrict__ qlen) {
    int b = blockIdx.y;
    int col = blockIdx.x * 256 + threadIdx.x;
    int kl = qlen[b];
    const float* Ab = g_A + ((size_t)b << 20) + col;
    float m[4] = {-1e30f, -1e30f, -1e30f, -1e30f}, s[4] = {0.f, 0.f, 0.f, 0.f};
    int q = 0;
    for (; q + 4 <= kl; q += 4) {
        #pragma unroll
        for (int i = 0; i < 4; i++) {
            float v = Ab[(size_t)(q + i) << 10];
            float nm = fmaxf(m[i], v);
            s[i] = s[i] * __expf(m[i] - nm) + __expf(v - nm);
            m[i] = nm;
        }
    }
    for (; q < kl; q++) {
        float v = Ab[(size_t)q << 10];
        float nm = fmaxf(m[0], v);
        s[0] = s[0] * __expf(m[0] - nm) + __expf(v - nm);
        m[0] = nm;
    }
    float M = fmaxf(fmaxf(m[0], m[1]), fmaxf(m[2], m[3]));
    float S = 0.f;
    #pragma unroll
    for (int i = 0; i < 4; i++) S += s[i] * __expf(m[i] - M);
    g_cmax[b * L + col] = M;
    g_cinv[b * L + col] = 1.f / S;
}

// ---------------------------------------------------------------------------
// Split-fp16 HMMA GEMM (mma.sync m16n8k16 f16, portable PTX path)
// Out[m][n] = sum_k A(m,k) * B(n,k); A split into NTA fp16 terms, B into NTB;
// NP product-term combinations accumulated into one fp32 accumulator.
// Block tile 128x128, warp tile 64x32 (2x4 warps), Kc=32, cp.async x2 buffer.
// ---------------------------------------------------------------------------
#define TILE_B 10240                       // 128 rows * 80B (64B data + 16B pad)

template <int NTA, int NTB, int NP>
__global__ __launch_bounds__(256, (NP == 1 ? 2 : 1)) void k_mma_fp16(
    const __half* __restrict__ A0, const __half* __restrict__ A1,
    const __half* __restrict__ B0, const __half* __restrict__ B1,
    const int* klen_arr, int klen_fixed, float* __restrict__ Out) {
    extern __shared__ char smem[];
    const uint32_t sbase = smem_u32(smem);
    constexpr int TOT = NTA + NTB;
    constexpr int STAGE = TOT * TILE_B;

    const int tid = threadIdx.x, lane = tid & 31, wid = tid >> 5;
    const int b = blockIdx.z, m0 = blockIdx.y * 128, n0 = blockIdx.x * 128;
    const int kl = klen_arr ? klen_arr[b] : klen_fixed;
    const int ktiles = (kl + 31) >> 5;

    const size_t boff = (size_t)b << 20;
    const __half* gp[TOT];
    gp[0] = A0 + boff + (size_t)m0 * L;
    if (NTA == 2) gp[1] = A1 + boff + (size_t)m0 * L;
    gp[NTA] = B0 + boff + (size_t)n0 * L;
    if (NTB == 2) gp[NTA + 1] = B1 + boff + (size_t)n0 * L;

    constexpr int PA3[3] = {0, 0, 1}, PB3[3] = {0, 1, 0};

    // warp layout: 2 (m) x 4 (n)
    const int warp_m = (wid >> 2) * 64;
    const int warp_n = (wid & 3) * 32;
    const int rowA = warp_m + (lane & 7) + ((lane >> 3) & 1) * 8;
    const int chA = (lane >> 4) & 1;
    const int rowB = warp_n + (lane & 7) + ((lane >> 4) & 1) * 8;
    const int chB = (lane >> 3) & 1;

    float acc[4][4][4] = {};   // [m-frag][n-frag][mma reg]

    auto load_stage = [&](int t, int buf) {
        const int k0 = t * 32;
        const uint32_t sb = sbase + buf * STAGE;
        #pragma unroll
        for (int tile = 0; tile < TOT; tile++)
            #pragma unroll
            for (int pp = 0; pp < 2; pp++) {
                int id = tid + pp * 256;
                int row = id >> 2, ch = id & 3;
                uint32_t sa = sb + tile * TILE_B + row * 80 + ch * 16;
                const __half* ga = gp[tile] + (size_t)row * L + k0 + ch * 8;
                CP_ASYNC16(sa, ga);
            }
    };

    load_stage(0, 0);
    CP_COMMIT();

    for (int t = 0; t < ktiles; t++) {
        if (t + 1 < ktiles) load_stage(t + 1, (t + 1) & 1);
        CP_COMMIT();
        CP_WAIT1();
        __syncthreads();

        const uint32_t sb = sbase + (t & 1) * STAGE;
        #pragma unroll
        for (int ks = 0; ks < 2; ks++) {
            uint32_t Bf[NTB][8];
            #pragma unroll
            for (int tm = 0; tm < NTB; tm++)
                #pragma unroll
                for (int g2 = 0; g2 < 2; g2++) {
                    uint32_t a = sb + (NTA + tm) * TILE_B + (rowB + g2 * 16) * 80
                               + (chB + 2 * ks) * 16;
                    LDSM4(Bf[tm][g2 * 4 + 0], Bf[tm][g2 * 4 + 1],
                          Bf[tm][g2 * 4 + 2], Bf[tm][g2 * 4 + 3], a);
                }
            uint32_t Af[16];
            #pragma unroll
            for (int p = 0; p < NP; p++) {
                const int pa = (NP == 3) ? PA3[p] : 0;
                const int pb = (NP == 3) ? PB3[p] : 0;
                const int pap = (p == 0) ? -1 : ((NP == 3) ? PA3[p - 1] : 0);
                if (pa != pap) {
                    #pragma unroll
                    for (int f = 0; f < 4; f++) {
                        uint32_t a = sb + pa * TILE_B + (rowA + f * 16) * 80
                                   + (chA + 2 * ks) * 16;
                        LDSM4(Af[f * 4 + 0], Af[f * 4 + 1], Af[f * 4 + 2], Af[f * 4 + 3], a);
                    }
                }
                #pragma unroll
                for (int f = 0; f < 4; f++)
                    #pragma unroll
                    for (int g = 0; g < 4; g++) {
                        uint32_t b0 = Bf[pb][(g >> 1) * 4 + (g & 1) * 2];
                        uint32_t b1 = Bf[pb][(g >> 1) * 4 + (g & 1) * 2 + 1];
                        mma16816(acc[f][g][0], acc[f][g][1], acc[f][g][2], acc[f][g][3],
                                 Af[f * 4], Af[f * 4 + 1], Af[f * 4 + 2], Af[f * 4 + 3],
                                 b0, b1);
                    }
            }
        }
        __syncthreads();
    }

    float* Ob = Out + boff;
    #pragma unroll
    for (int f = 0; f < 4; f++)
        #pragma unroll
        for (int g = 0; g < 4; g++) {
            int row = m0 + warp_m + f * 16 + (lane >> 2);
            int col = n0 + warp_n + g * 8 + (lane & 3) * 2;
            *(float2*)(Ob + (size_t)row * L + col) = make_float2(acc[f][g][0], acc[f][g][1]);
            *(float2*)(Ob + (size_t)(row + 8) * L + col) = make_float2(acc[f][g][2], acc[f][g][3]);
        }
}

// ---------------------------------------------------------------------------
extern "C" void kernel_launch(void* const* d_in, const int* in_sizes, int n_in,
                              void* d_out, int out_size) {
    const float* q = (const float*)d_in[0];
    const float* dmat = (const float*)d_in[1];
    const int* qlen = (const int*)d_in[2];
    const int* dlen = (const int*)d_in[3];

    float* out = (float*)d_out;
    const size_t ten = (size_t)BATCH * L * HD;
    float* out_cd = out;
    float* out_sq = out + ten;
    float* out_sd = out + 2 * ten;

    void *pA, *pq0, *pq1, *pd0, *pd1, *pdT, *pqT, *psT, *pwr, *pwc;
    cudaGetSymbolAddress(&pA, g_A);
    cudaGetSymbolAddress(&pq0, g_q0); cudaGetSymbolAddress(&pq1, g_q1);
    cudaGetSymbolAddress(&pd0, g_d0); cudaGetSymbolAddress(&pd1, g_d1);
    cudaGetSymbolAddress(&pdT, g_dT); cudaGetSymbolAddress(&pqT, g_qT);
    cudaGetSymbolAddress(&psT, g_sT);
    cudaGetSymbolAddress(&pwr, g_wr); cudaGetSymbolAddress(&pwc, g_wc);

    const int SMEM4 = 2 * 4 * TILE_B;   // 81920  (K1: 2+2 terms)
    const int SMEM2 = 2 * 2 * TILE_B;   // 40960  (K3-5: 1+1 terms)
    cudaFuncSetAttribute(k_mma_fp16<2, 2, 3>, cudaFuncAttributeMaxDynamicSharedMemorySize, SMEM4);
    cudaFuncSetAttribute(k_mma_fp16<1, 1, 1>, cudaFuncAttributeMaxDynamicSharedMemorySize, SMEM2);

    dim3 gg(HD / 128, L / 128, BATCH);
    dim3 tg(32, 32, 32), tb(32, 8);
    int nsplit = (int)(NEL / 4 / 256);

    // 1) 2-way fp16 splits of inputs (K1 operands)
    k_split2h<<<nsplit, 256>>>((const float4*)q, (uint2*)pq0, (uint2*)pq1);
    k_split2h<<<nsplit, 256>>>((const float4*)dmat, (uint2*)pd0, (uint2*)pd1);

    // 2) K1: A = q @ d^T   (fp32-grade via 3 fp16 product terms)
    k_mma_fp16<2, 2, 3><<<gg, 256, SMEM4>>>(
        (const __half*)pq0, (const __half*)pq1,
        (const __half*)pd0, (const __half*)pd1,
        nullptr, L, (float*)pA);

    // 3) softmax stats
    k_row_stats<<<dim3(L / 8, BATCH), 256>>>(dlen);
    k_col_stats<<<dim3(L / 256, BATCH), 256>>>(qlen);

    // 4) fused weight generation (wr natural + wc transposed, single fp16)
    k_weights<<<tg, tb>>>(qlen, dlen);

    // 5) transposed single-fp16 B operands
    k_splitT1h<<<tg, tb>>>(dmat, (__half*)pdT);
    k_splitT1h<<<tg, tb>>>(q, (__half*)pqT);

    // 6) K3: sq^T = Wr @ d^T
    k_mma_fp16<1, 1, 1><<<gg, 256, SMEM2>>>(
        (const __half*)pwr, nullptr, (const __half*)pdT, nullptr,
        dlen, 0, out_sq);

    // 7) K4: sd^T = Wc @ q^T
    k_mma_fp16<1, 1, 1><<<gg, 256, SMEM2>>>(
        (const __half*)pwc, nullptr, (const __half*)pqT, nullptr,
        qlen, 0, out_sd);

    // 8) K5: cd^T = Wc @ sq^T
    k_splitT1h<<<tg, tb>>>(out_sq, (__half*)psT);
    k_mma_fp16<1, 1, 1><<<gg, 256, SMEM2>>>(
        (const __half*)pwc, nullptr, (const __half*)psT, nullptr,
        qlen, 0, out_cd);
}

// round 6
// speedup vs baseline: 6.0203x; 1.2741x over previous
#include <cuda_runtime.h>
#include <cuda_fp16.h>
#include <cstdint>

#define BATCH 32
#define L 1024
#define HD 1024

// ---------------------------------------------------------------------------
// Scratch (__device__ globals; no runtime allocation)
// ---------------------------------------------------------------------------
__device__ float g_A[(size_t)BATCH * L * L];   // raw logits, 128 MB
__device__ float g_rmax[BATCH * L];
__device__ float g_rinv[BATCH * L];
__device__ float g_cmax[BATCH * L];
__device__ float g_cinv[BATCH * L];

#define NEL ((size_t)BATCH * L * HD)
__device__ __half g_q0[NEL], g_q1[NEL];   // q 2-way fp16 split (natural [q][h])
__device__ __half g_d0[NEL], g_d1[NEL];   // d 2-way fp16 split (natural [dp][h])
__device__ __half g_s[NEL];               // sq^T fp16 copy (natural [q][h])
__device__ __half g_wr[NEL];              // row-softmax weights [q][dp], fp16
__device__ __half g_wc[NEL];              // col-softmax weights [q][dp] NATURAL, fp16

// ---------------------------------------------------------------------------
// Helpers
// ---------------------------------------------------------------------------
__device__ __forceinline__ uint32_t smem_u32(const void* p) {
    uint32_t a;
    asm("{ .reg .u64 t; cvta.to.shared.u64 t, %1; cvt.u32.u64 %0, t; }" : "=r"(a) : "l"(p));
    return a;
}

#define LDSM4(R0, R1, R2, R3, addr)                                             \
    asm volatile("ldmatrix.sync.aligned.m8n8.x4.shared.b16 {%0,%1,%2,%3}, [%4];" \
                 : "=r"(R0), "=r"(R1), "=r"(R2), "=r"(R3) : "r"(addr))
#define LDSM4T(R0, R1, R2, R3, addr)                                                  \
    asm volatile("ldmatrix.sync.aligned.m8n8.x4.trans.shared.b16 {%0,%1,%2,%3}, [%4];" \
                 : "=r"(R0), "=r"(R1), "=r"(R2), "=r"(R3) : "r"(addr))

#define CP_ASYNC16(saddr, gaddr) \
    asm volatile("cp.async.cg.shared.global [%0], [%1], 16;" :: "r"(saddr), "l"(gaddr))
#define CP_COMMIT() asm volatile("cp.async.commit_group;" ::: "memory")
#define CP_WAIT1()  asm volatile("cp.async.wait_group 1;" ::: "memory")

__device__ __forceinline__ void mma16816(float& c0, float& c1, float& c2, float& c3,
                                         uint32_t a0, uint32_t a1, uint32_t a2, uint32_t a3,
                                         uint32_t b0, uint32_t b1) {
    asm volatile(
        "mma.sync.aligned.m16n8k16.row.col.f32.f16.f16.f32 "
        "{%0,%1,%2,%3}, {%4,%5,%6,%7}, {%8,%9}, {%0,%1,%2,%3};"
        : "+f"(c0), "+f"(c1), "+f"(c2), "+f"(c3)
        : "r"(a0), "r"(a1), "r"(a2), "r"(a3), "r"(b0), "r"(b1));
}

// ---------------------------------------------------------------------------
// Conversion kernels
// ---------------------------------------------------------------------------
union HU4 { __half h[4]; uint2 u; };

// fp32 -> 2-way fp16 split, natural layout
__global__ __launch_bounds__(256) void k_split2h(const float4* __restrict__ x,
                                                 uint2* __restrict__ o0,
                                                 uint2* __restrict__ o1) {
    size_t i = (size_t)blockIdx.x * 256 + threadIdx.x;
    float4 v = x[i];
    float xs[4] = {v.x, v.y, v.z, v.w};
    HU4 p0, p1;
    #pragma unroll
    for (int c = 0; c < 4; c++) {
        p0.h[c] = __float2half_rn(xs[c]);
        p1.h[c] = __float2half_rn(xs[c] - __half2float(p0.h[c]));
    }
    o0[i] = p0.u;
    o1[i] = p1.u;
}

// Streaming weight generation (both NATURAL [q][dp], fully coalesced):
//   wr[q][dp] = exp(A - rmax[q]) * rinv[q]    (0 for dp >= dlen)
//   wc[q][dp] = exp(A - cmax[dp]) * cinv[dp]  (0 for q  >= qlen)
__global__ __launch_bounds__(256) void k_weights(const int* __restrict__ qlen,
                                                 const int* __restrict__ dlen) {
    int b = blockIdx.y, qq = blockIdx.x, tid = threadIdx.x;
    int klq = qlen[b], kld = dlen[b];
    float rm = g_rmax[b * L + qq], ri = g_rinv[b * L + qq];
    size_t base = ((size_t)b << 20) + ((size_t)qq << 10);
    float4 v = *(const float4*)(g_A + base + tid * 4);
    float4 cm = *(const float4*)(g_cmax + b * L + tid * 4);
    float4 ci = *(const float4*)(g_cinv + b * L + tid * 4);
    float xs[4] = {v.x, v.y, v.z, v.w};
    float cms[4] = {cm.x, cm.y, cm.z, cm.w};
    float cis[4] = {ci.x, ci.y, ci.z, ci.w};
    HU4 pr, pc;
    bool qv = qq < klq;
    #pragma unroll
    for (int c = 0; c < 4; c++) {
        int dp = tid * 4 + c;
        float wr = (dp < kld) ? __expf(xs[c] - rm) * ri : 0.f;
        float wc = qv ? __expf(xs[c] - cms[c]) * cis[c] : 0.f;
        pr.h[c] = __float2half_rn(wr);
        pc.h[c] = __float2half_rn(wc);
    }
    size_t oi = (base >> 2) + tid;
    ((uint2*)g_wr)[oi] = pr.u;
    ((uint2*)g_wc)[oi] = pc.u;
}

// ---------------------------------------------------------------------------
// Softmax statistics
// ---------------------------------------------------------------------------
__global__ __launch_bounds__(256) void k_row_stats(const int* __restrict__ dlen) {
    int b = blockIdx.y;
    int row = blockIdx.x * 8 + (threadIdx.x >> 5);
    int lane = threadIdx.x & 31;
    int kl = dlen[b];
    const float4* Ar = (const float4*)(g_A + ((size_t)b << 20) + ((size_t)row << 10));
    float v[32];
    #pragma unroll
    for (int i = 0; i < 8; i++) {
        float4 t = Ar[lane + i * 32];
        v[i * 4 + 0] = t.x; v[i * 4 + 1] = t.y; v[i * 4 + 2] = t.z; v[i * 4 + 3] = t.w;
    }
    float m = -1e30f;
    #pragma unroll
    for (int i = 0; i < 8; i++)
        #pragma unroll
        for (int c = 0; c < 4; c++) {
            int idx = (lane + i * 32) * 4 + c;
            if (idx >= kl) v[i * 4 + c] = -1e30f;
            m = fmaxf(m, v[i * 4 + c]);
        }
    #pragma unroll
    for (int off = 16; off; off >>= 1) m = fmaxf(m, __shfl_xor_sync(~0u, m, off));
    float s = 0.f;
    #pragma unroll
    for (int i = 0; i < 32; i++) s += __expf(v[i] - m);
    #pragma unroll
    for (int off = 16; off; off >>= 1) s += __shfl_xor_sync(~0u, s, off);
    if (lane == 0) {
        g_rmax[b * L + row] = m;
        g_rinv[b * L + row] = 1.f / s;
    }
}

__global__ __launch_bounds__(256) void k_col_stats(const int* __restrict__ qlen) {
    int b = blockIdx.y;
    int col = blockIdx.x * 256 + threadIdx.x;
    int kl = qlen[b];
    const float* Ab = g_A + ((size_t)b << 20) + col;
    float m[4] = {-1e30f, -1e30f, -1e30f, -1e30f}, s[4] = {0.f, 0.f, 0.f, 0.f};
    int q = 0;
    for (; q + 4 <= kl; q += 4) {
        #pragma unroll
        for (int i = 0; i < 4; i++) {
            float v = Ab[(size_t)(q + i) << 10];
            float nm = fmaxf(m[i], v);
            s[i] = s[i] * __expf(m[i] - nm) + __expf(v - nm);
            m[i] = nm;
        }
    }
    for (; q < kl; q++) {
        float v = Ab[(size_t)q << 10];
        float nm = fmaxf(m[0], v);
        s[0] = s[0] * __expf(m[0] - nm) + __expf(v - nm);
        m[0] = nm;
    }
    float M = fmaxf(fmaxf(m[0], m[1]), fmaxf(m[2], m[3]));
    float S = 0.f;
    #pragma unroll
    for (int i = 0; i < 4; i++) S += s[i] * __expf(m[i] - M);
    g_cmax[b * L + col] = M;
    g_cinv[b * L + col] = 1.f / S;
}

// ---------------------------------------------------------------------------
// Split-fp16 HMMA GEMM. Out[m][n] = sum_k A(m,k) * B(n,k).
// TA/TB: 0 = operand stored K-major natural ([m][k] / [n][k]),
//        1 = operand stored k-row natural ([k][m] / [k][n]) -> ldmatrix.trans.
// Block 128x128, warp tile 64x32 (2x4 warps), Kc=64, cp.async double buffer.
// Natural tile: 128 rows * 144B (128B data + 16 pad). Trans tile: 64 rows * 256B,
// chunk-XOR swizzle (ch ^= k&7) for conflict-free ldmatrix.trans.
// ---------------------------------------------------------------------------
#define NAT_TB 18432
#define TRN_TB 16384

template <int NTA, int NTB, int NP, int TA, int TB, int EPI16>
__global__ __launch_bounds__(256, (NP == 1 ? 2 : 1)) void k_mma(
    const __half* __restrict__ A0, const __half* __restrict__ A1,
    const __half* __restrict__ B0, const __half* __restrict__ B1,
    const int* klen_arr, int klen_fixed,
    float* __restrict__ Out, __half* __restrict__ Out16) {
    extern __shared__ char smem[];
    const uint32_t sbase = smem_u32(smem);
    constexpr int ATB = TA ? TRN_TB : NAT_TB;
    constexpr int BTB = TB ? TRN_TB : NAT_TB;
    constexpr int STAGE = NTA * ATB + NTB * BTB;

    const int tid = threadIdx.x, lane = tid & 31, wid = tid >> 5;
    const int b = blockIdx.z, m0 = blockIdx.y * 128, n0 = blockIdx.x * 128;
    const int kl = klen_arr ? klen_arr[b] : klen_fixed;
    const int ktiles = (kl + 63) >> 6;

    const size_t boff = (size_t)b << 20;
    const __half* gpA[NTA];
    const __half* gpB[NTB];
    gpA[0] = A0 + boff + (TA ? (size_t)m0 : (size_t)m0 * L);
    if (NTA == 2) gpA[1] = A1 + boff + (TA ? (size_t)m0 : (size_t)m0 * L);
    gpB[0] = B0 + boff + (TB ? (size_t)n0 : (size_t)n0 * L);
    if (NTB == 2) gpB[1] = B1 + boff + (TB ? (size_t)n0 : (size_t)n0 * L);

    constexpr int PA3[3] = {0, 0, 1}, PB3[3] = {0, 1, 0};

    // warp layout: 2 (m) x 4 (n)
    const int warp_m = (wid >> 2) * 64;
    const int warp_n = (wid & 3) * 32;
    // natural-path lane addressing
    const int rowA = warp_m + (lane & 7) + ((lane >> 3) & 1) * 8;
    const int chA = (lane >> 4) & 1;
    const int rowB = warp_n + (lane & 7) + ((lane >> 4) & 1) * 8;
    const int chB = (lane >> 3) & 1;
    // trans-path lane addressing
    const int kArow = (lane & 7) + ((lane >> 4) & 1) * 8;   // within k16
    const int mA8 = ((lane >> 3) & 1) * 8;
    const int kBrow = (lane & 7) + ((lane >> 3) & 1) * 8;
    const int nB8 = ((lane >> 4) & 1) * 8;
    const int lsw = (lane & 7) << 4;                        // swizzle term

    float acc[4][4][4] = {};

    auto load_stage = [&](int t, int buf) {
        const int k0 = t * 64;
        uint32_t sb = sbase + buf * STAGE;
        #pragma unroll
        for (int a = 0; a < NTA; a++) {
            uint32_t tb = sb + a * ATB;
            #pragma unroll
            for (int pp = 0; pp < 4; pp++) {
                int id = tid + pp * 256;
                if (!TA) {
                    int row = id >> 3, ch = id & 7;
                    CP_ASYNC16(tb + row * 144 + ch * 16,
                               gpA[a] + (size_t)row * L + k0 + ch * 8);
                } else {
                    int kr = id >> 4, ch = id & 15;
                    CP_ASYNC16(tb + kr * 256 + ((ch ^ (kr & 7)) << 4),
                               gpA[a] + (size_t)(k0 + kr) * L + ch * 8);
                }
            }
        }
        sb += NTA * ATB;
        #pragma unroll
        for (int a = 0; a < NTB; a++) {
            uint32_t tb = sb + a * BTB;
            #pragma unroll
            for (int pp = 0; pp < 4; pp++) {
                int id = tid + pp * 256;
                if (!TB) {
                    int row = id >> 3, ch = id & 7;
                    CP_ASYNC16(tb + row * 144 + ch * 16,
                               gpB[a] + (size_t)row * L + k0 + ch * 8);
                } else {
                    int kr = id >> 4, ch = id & 15;
                    CP_ASYNC16(tb + kr * 256 + ((ch ^ (kr & 7)) << 4),
                               gpB[a] + (size_t)(k0 + kr) * L + ch * 8);
                }
            }
        }
    };

    load_stage(0, 0);
    CP_COMMIT();

    for (int t = 0; t < ktiles; t++) {
        if (t + 1 < ktiles) load_stage(t + 1, (t + 1) & 1);
        CP_COMMIT();
        CP_WAIT1();
        __syncthreads();

        const uint32_t sb = sbase + (t & 1) * STAGE;
        const uint32_t sbB = sb + NTA * ATB;
        #pragma unroll
        for (int ks = 0; ks < 4; ks++) {
            uint32_t Bf[NTB][8];
            #pragma unroll
            for (int tm = 0; tm < NTB; tm++)
                #pragma unroll
                for (int g2 = 0; g2 < 2; g2++) {
                    if (!TB) {
                        uint32_t a = sbB + tm * BTB + (rowB + g2 * 16) * 144
                                   + chB * 16 + ks * 32;
                        LDSM4(Bf[tm][g2 * 4 + 0], Bf[tm][g2 * 4 + 1],
                              Bf[tm][g2 * 4 + 2], Bf[tm][g2 * 4 + 3], a);
                    } else {
                        int n_off = warp_n + g2 * 16 + nB8;
                        int kr = ks * 16 + kBrow;
                        uint32_t a = sbB + tm * BTB + kr * 256
                                   + (((n_off >> 3) << 4) ^ lsw);
                        LDSM4T(Bf[tm][g2 * 4 + 0], Bf[tm][g2 * 4 + 1],
                               Bf[tm][g2 * 4 + 2], Bf[tm][g2 * 4 + 3], a);
                    }
                }
            uint32_t Af[16];
            #pragma unroll
            for (int p = 0; p < NP; p++) {
                const int pa = (NP == 3) ? PA3[p] : 0;
                const int pb = (NP == 3) ? PB3[p] : 0;
                const int pap = (p == 0) ? -1 : ((NP == 3) ? PA3[p - 1] : 0);
                if (pa != pap) {
                    #pragma unroll
                    for (int f = 0; f < 4; f++) {
                        if (!TA) {
                            uint32_t a = sb + pa * ATB + (rowA + f * 16) * 144
                                       + chA * 16 + ks * 32;
                            LDSM4(Af[f * 4 + 0], Af[f * 4 + 1],
                                  Af[f * 4 + 2], Af[f * 4 + 3], a);
                        } else {
                            int m_off = warp_m + f * 16 + mA8;
                            int kr = ks * 16 + kArow;
                            uint32_t a = sb + pa * ATB + kr * 256
                                       + (((m_off >> 3) << 4) ^ lsw);
                            LDSM4T(Af[f * 4 + 0], Af[f * 4 + 1],
                                   Af[f * 4 + 2], Af[f * 4 + 3], a);
                        }
                    }
                }
                #pragma unroll
                for (int f = 0; f < 4; f++)
                    #pragma unroll
                    for (int g = 0; g < 4; g++) {
                        uint32_t b0 = Bf[pb][(g >> 1) * 4 + (g & 1) * 2];
                        uint32_t b1 = Bf[pb][(g >> 1) * 4 + (g & 1) * 2 + 1];
                        mma16816(acc[f][g][0], acc[f][g][1], acc[f][g][2], acc[f][g][3],
                                 Af[f * 4], Af[f * 4 + 1], Af[f * 4 + 2], Af[f * 4 + 3],
                                 b0, b1);
                    }
            }
        }
        __syncthreads();
    }

    float* Ob = Out + boff;
    #pragma unroll
    for (int f = 0; f < 4; f++)
        #pragma unroll
        for (int g = 0; g < 4; g++) {
            int row = m0 + warp_m + f * 16 + (lane >> 2);
            int col = n0 + warp_n + g * 8 + (lane & 3) * 2;
            *(float2*)(Ob + (size_t)row * L + col) = make_float2(acc[f][g][0], acc[f][g][1]);
            *(float2*)(Ob + (size_t)(row + 8) * L + col) = make_float2(acc[f][g][2], acc[f][g][3]);
            if (EPI16) {
                __half* Oh = Out16 + boff;
                *(__half2*)(Oh + (size_t)row * L + col) =
                    __floats2half2_rn(acc[f][g][0], acc[f][g][1]);
                *(__half2*)(Oh + (size_t)(row + 8) * L + col) =
                    __floats2half2_rn(acc[f][g][2], acc[f][g][3]);
            }
        }
}

// ---------------------------------------------------------------------------
extern "C" void kernel_launch(void* const* d_in, const int* in_sizes, int n_in,
                              void* d_out, int out_size) {
    const float* q = (const float*)d_in[0];
    const float* dmat = (const float*)d_in[1];
    const int* qlen = (const int*)d_in[2];
    const int* dlen = (const int*)d_in[3];

    float* out = (float*)d_out;
    const size_t ten = (size_t)BATCH * L * HD;
    float* out_cd = out;
    float* out_sq = out + ten;
    float* out_sd = out + 2 * ten;

    void *pA, *pq0, *pq1, *pd0, *pd1, *ps, *pwr, *pwc;
    cudaGetSymbolAddress(&pA, g_A);
    cudaGetSymbolAddress(&pq0, g_q0); cudaGetSymbolAddress(&pq1, g_q1);
    cudaGetSymbolAddress(&pd0, g_d0); cudaGetSymbolAddress(&pd1, g_d1);
    cudaGetSymbolAddress(&ps, g_s);
    cudaGetSymbolAddress(&pwr, g_wr); cudaGetSymbolAddress(&pwc, g_wc);

    const int SMEM_K1 = 2 * (2 * NAT_TB + 2 * NAT_TB);   // 147456
    const int SMEM_K3 = 2 * (NAT_TB + TRN_TB);           // 69632
    const int SMEM_K45 = 2 * (TRN_TB + TRN_TB);          // 65536
    cudaFuncSetAttribute(k_mma<2, 2, 3, 0, 0, 0>,
                         cudaFuncAttributeMaxDynamicSharedMemorySize, SMEM_K1);
    cudaFuncSetAttribute(k_mma<1, 1, 1, 0, 1, 1>,
                         cudaFuncAttributeMaxDynamicSharedMemorySize, SMEM_K3);
    cudaFuncSetAttribute(k_mma<1, 1, 1, 1, 1, 0>,
                         cudaFuncAttributeMaxDynamicSharedMemorySize, SMEM_K45);

    dim3 gg(HD / 128, L / 128, BATCH);
    int nsplit = (int)(NEL / 4 / 256);

    // 1) 2-way fp16 splits (hi terms double as natural fp16 q/d for trans loads)
    k_split2h<<<nsplit, 256>>>((const float4*)q, (uint2*)pq0, (uint2*)pq1);
    k_split2h<<<nsplit, 256>>>((const float4*)dmat, (uint2*)pd0, (uint2*)pd1);

    // 2) K1: A = q @ d^T   (fp32-grade via 3 fp16 product terms)
    k_mma<2, 2, 3, 0, 0, 0><<<gg, 256, SMEM_K1>>>(
        (const __half*)pq0, (const __half*)pq1,
        (const __half*)pd0, (const __half*)pd1,
        nullptr, L, (float*)pA, nullptr);

    // 3) softmax stats
    k_row_stats<<<dim3(L / 8, BATCH), 256>>>(dlen);
    k_col_stats<<<dim3(L / 256, BATCH), 256>>>(qlen);

    // 4) fused streaming weights (wr + wc, both natural fp16)
    k_weights<<<dim3(L, BATCH), 256>>>(qlen, dlen);

    // 5) K3: sq^T = Wr @ d^T  (A natural, B=d trans; epilogue also emits fp16 sq^T)
    k_mma<1, 1, 1, 0, 1, 1><<<gg, 256, SMEM_K3>>>(
        (const __half*)pwr, nullptr, (const __half*)pd0, nullptr,
        dlen, 0, out_sq, (__half*)ps);

    // 6) K4: sd^T = Wc @ q^T  (A=wc trans, B=q trans)
    k_mma<1, 1, 1, 1, 1, 0><<<gg, 256, SMEM_K45>>>(
        (const __half*)pwc, nullptr, (const __half*)pq0, nullptr,
        qlen, 0, out_sd, nullptr);

    // 7) K5: cd^T = Wc @ sq^T (A=wc trans, B=sq^T fp16 trans)
    k_mma<1, 1, 1, 1, 1, 0><<<gg, 256, SMEM_K45>>>(
        (const __half*)pwc, nullptr, (const __half*)ps, nullptr,
        qlen, 0, out_cd, nullptr);
}

// round 8
// speedup vs baseline: 6.1727x; 1.0253x over previous
#include <cuda_runtime.h>
#include <cuda_fp16.h>
#include <cstdint>

#define BATCH 32
#define L 1024
#define HD 1024

// ---------------------------------------------------------------------------
// Scratch (__device__ globals; no runtime allocation)
// ---------------------------------------------------------------------------
__device__ float g_A[(size_t)BATCH * L * L];   // raw logits, 128 MB
__device__ float g_rmax[BATCH * L];
__device__ float g_rinv[BATCH * L];
__device__ float g_cmax[BATCH * L];
__device__ float g_cinv[BATCH * L];

#define NEL ((size_t)BATCH * L * HD)
__device__ __half g_q0[NEL], g_q1[NEL];   // q 2-way fp16 split (natural [q][h])
__device__ __half g_d0[NEL], g_d1[NEL];   // d 2-way fp16 split (natural [dp][h])
__device__ __half g_s[NEL];               // sq^T fp16 copy (natural [q][h])
__device__ __half g_wr[NEL];              // row-softmax weights [q][dp], fp16
__device__ __half g_wc[NEL];              // col-softmax weights [q][dp] NATURAL, fp16

// ---------------------------------------------------------------------------
// Helpers
// ---------------------------------------------------------------------------
__device__ __forceinline__ uint32_t smem_u32(const void* p) {
    uint32_t a;
    asm("{ .reg .u64 t; cvta.to.shared.u64 t, %1; cvt.u32.u64 %0, t; }" : "=r"(a) : "l"(p));
    return a;
}

#define LDSM4(R0, R1, R2, R3, addr)                                             \
    asm volatile("ldmatrix.sync.aligned.m8n8.x4.shared.b16 {%0,%1,%2,%3}, [%4];" \
                 : "=r"(R0), "=r"(R1), "=r"(R2), "=r"(R3) : "r"(addr))
#define LDSM4T(R0, R1, R2, R3, addr)                                                  \
    asm volatile("ldmatrix.sync.aligned.m8n8.x4.trans.shared.b16 {%0,%1,%2,%3}, [%4];" \
                 : "=r"(R0), "=r"(R1), "=r"(R2), "=r"(R3) : "r"(addr))

#define CP_ASYNC16(saddr, gaddr) \
    asm volatile("cp.async.cg.shared.global [%0], [%1], 16;" :: "r"(saddr), "l"(gaddr))
#define CP_COMMIT() asm volatile("cp.async.commit_group;" ::: "memory")
#define CP_WAIT0()  asm volatile("cp.async.wait_group 0;" ::: "memory")

__device__ __forceinline__ void mma16816(float& c0, float& c1, float& c2, float& c3,
                                         uint32_t a0, uint32_t a1, uint32_t a2, uint32_t a3,
                                         uint32_t b0, uint32_t b1) {
    asm volatile(
        "mma.sync.aligned.m16n8k16.row.col.f32.f16.f16.f32 "
        "{%0,%1,%2,%3}, {%4,%5,%6,%7}, {%8,%9}, {%0,%1,%2,%3};"
        : "+f"(c0), "+f"(c1), "+f"(c2), "+f"(c3)
        : "r"(a0), "r"(a1), "r"(a2), "r"(a3), "r"(b0), "r"(b1));
}

// ---------------------------------------------------------------------------
// Conversion kernels
// ---------------------------------------------------------------------------
union HU4 { __half h[4]; uint2 u; };

// fp32 -> 2-way fp16 split, natural layout
__global__ __launch_bounds__(256) void k_split2h(const float4* __restrict__ x,
                                                 uint2* __restrict__ o0,
                                                 uint2* __restrict__ o1) {
    size_t i = (size_t)blockIdx.x * 256 + threadIdx.x;
    float4 v = x[i];
    float xs[4] = {v.x, v.y, v.z, v.w};
    HU4 p0, p1;
    #pragma unroll
    for (int c = 0; c < 4; c++) {
        p0.h[c] = __float2half_rn(xs[c]);
        p1.h[c] = __float2half_rn(xs[c] - __half2float(p0.h[c]));
    }
    o0[i] = p0.u;
    o1[i] = p1.u;
}

// Streaming weight generation (both NATURAL [q][dp], fully coalesced):
//   wr[q][dp] = exp(A - rmax[q]) * rinv[q]    (0 for dp >= dlen)
//   wc[q][dp] = exp(A - cmax[dp]) * cinv[dp]  (0 for q  >= qlen)
__global__ __launch_bounds__(256) void k_weights(const int* __restrict__ qlen,
                                                 const int* __restrict__ dlen) {
    int b = blockIdx.y, qq = blockIdx.x, tid = threadIdx.x;
    int klq = qlen[b], kld = dlen[b];
    float rm = g_rmax[b * L + qq], ri = g_rinv[b * L + qq];
    size_t base = ((size_t)b << 20) + ((size_t)qq << 10);
    float4 v = *(const float4*)(g_A + base + tid * 4);
    float4 cm = *(const float4*)(g_cmax + b * L + tid * 4);
    float4 ci = *(const float4*)(g_cinv + b * L + tid * 4);
    float xs[4] = {v.x, v.y, v.z, v.w};
    float cms[4] = {cm.x, cm.y, cm.z, cm.w};
    float cis[4] = {ci.x, ci.y, ci.z, ci.w};
    HU4 pr, pc;
    bool qv = qq < klq;
    #pragma unroll
    for (int c = 0; c < 4; c++) {
        int dp = tid * 4 + c;
        float wr = (dp < kld) ? __expf(xs[c] - rm) * ri : 0.f;
        float wc = qv ? __expf(xs[c] - cms[c]) * cis[c] : 0.f;
        pr.h[c] = __float2half_rn(wr);
        pc.h[c] = __float2half_rn(wc);
    }
    size_t oi = (base >> 2) + tid;
    ((uint2*)g_wr)[oi] = pr.u;
    ((uint2*)g_wc)[oi] = pc.u;
}

// ---------------------------------------------------------------------------
// Softmax statistics
// ---------------------------------------------------------------------------
__global__ __launch_bounds__(256) void k_row_stats(const int* __restrict__ dlen) {
    int b = blockIdx.y;
    int row = blockIdx.x * 8 + (threadIdx.x >> 5);
    int lane = threadIdx.x & 31;
    int kl = dlen[b];
    const float4* Ar = (const float4*)(g_A + ((size_t)b << 20) + ((size_t)row << 10));
    float v[32];
    #pragma unroll
    for (int i = 0; i < 8; i++) {
        float4 t = Ar[lane + i * 32];
        v[i * 4 + 0] = t.x; v[i * 4 + 1] = t.y; v[i * 4 + 2] = t.z; v[i * 4 + 3] = t.w;
    }
    float m = -1e30f;
    #pragma unroll
    for (int i = 0; i < 8; i++)
        #pragma unroll
        for (int c = 0; c < 4; c++) {
            int idx = (lane + i * 32) * 4 + c;
            if (idx >= kl) v[i * 4 + c] = -1e30f;
            m = fmaxf(m, v[i * 4 + c]);
        }
    #pragma unroll
    for (int off = 16; off; off >>= 1) m = fmaxf(m, __shfl_xor_sync(~0u, m, off));
    float s = 0.f;
    #pragma unroll
    for (int i = 0; i < 32; i++) s += __expf(v[i] - m);
    #pragma unroll
    for (int off = 16; off; off >>= 1) s += __shfl_xor_sync(~0u, s, off);
    if (lane == 0) {
        g_rmax[b * L + row] = m;
        g_rinv[b * L + row] = 1.f / s;
    }
}

__global__ __launch_bounds__(256) void k_col_stats(const int* __restrict__ qlen) {
    int b = blockIdx.y;
    int col = blockIdx.x * 256 + threadIdx.x;
    int kl = qlen[b];
    const float* Ab = g_A + ((size_t)b << 20) + col;
    float m[4] = {-1e30f, -1e30f, -1e30f, -1e30f}, s[4] = {0.f, 0.f, 0.f, 0.f};
    int q = 0;
    for (; q + 4 <= kl; q += 4) {
        #pragma unroll
        for (int i = 0; i < 4; i++) {
            float v = Ab[(size_t)(q + i) << 10];
            float nm = fmaxf(m[i], v);
            s[i] = s[i] * __expf(m[i] - nm) + __expf(v - nm);
            m[i] = nm;
        }
    }
    for (; q < kl; q++) {
        float v = Ab[(size_t)q << 10];
        float nm = fmaxf(m[0], v);
        s[0] = s[0] * __expf(m[0] - nm) + __expf(v - nm);
        m[0] = nm;
    }
    float M = fmaxf(fmaxf(m[0], m[1]), fmaxf(m[2], m[3]));
    float S = 0.f;
    #pragma unroll
    for (int i = 0; i < 4; i++) S += s[i] * __expf(m[i] - M);
    g_cmax[b * L + col] = M;
    g_cinv[b * L + col] = 1.f / S;
}

// ---------------------------------------------------------------------------
// Split-fp16 HMMA GEMM. Out[m][n] = sum_k A(m,k) * B(n,k).
// TA/TB: 0 = K-major natural ([m][k]/[n][k]) -> ldmatrix;
//        1 = k-row natural ([k][m]/[k][n])   -> ldmatrix.trans.
// Block 128x128, warp tile 64x32 (2x4 warps), Kc templated, cp.async x2 buffer.
// Single __syncthreads per k-chunk: wait_group 0 -> sync -> prefetch -> compute.
// ---------------------------------------------------------------------------
template <int NTA, int NTB, int NP, int TA, int TB, int EPI16, int KC>
__global__ __launch_bounds__(256, 2) void k_mma(
    const __half* __restrict__ A0, const __half* __restrict__ A1,
    const __half* __restrict__ B0, const __half* __restrict__ B1,
    const int* klen_arr, int klen_fixed,
    float* __restrict__ Out, __half* __restrict__ Out16) {
    extern __shared__ char smem[];
    const uint32_t sbase = smem_u32(smem);
    constexpr int NAT_RB = KC * 2 + 16;          // natural row bytes (pad 16)
    constexpr int NAT_TB = 128 * NAT_RB;
    constexpr int TRN_TB = KC * 256;
    constexpr int ATB = TA ? TRN_TB : NAT_TB;
    constexpr int BTB = TB ? TRN_TB : NAT_TB;
    constexpr int STAGE = NTA * ATB + NTB * BTB;
    constexpr int CPR = KC / 8;                  // 16B chunks per natural row
    constexpr int OPS = KC * 16 / 256;           // cp.async per thread per tile
    constexpr int KSN = KC / 16;                 // k16 steps per chunk

    const int tid = threadIdx.x, lane = tid & 31, wid = tid >> 5;
    const int b = blockIdx.z, m0 = blockIdx.y * 128, n0 = blockIdx.x * 128;
    const int kl = klen_arr ? klen_arr[b] : klen_fixed;
    const int ktiles = (kl + KC - 1) / KC;

    const size_t boff = (size_t)b << 20;
    const __half* gpA[NTA];
    const __half* gpB[NTB];
    gpA[0] = A0 + boff + (TA ? (size_t)m0 : (size_t)m0 * L);
    if (NTA == 2) gpA[1] = A1 + boff + (TA ? (size_t)m0 : (size_t)m0 * L);
    gpB[0] = B0 + boff + (TB ? (size_t)n0 : (size_t)n0 * L);
    if (NTB == 2) gpB[1] = B1 + boff + (TB ? (size_t)n0 : (size_t)n0 * L);

    constexpr int PA3[3] = {0, 0, 1}, PB3[3] = {0, 1, 0};

    // warp layout: 2 (m) x 4 (n)
    const int warp_m = (wid >> 2) * 64;
    const int warp_n = (wid & 3) * 32;
    // natural-path lane addressing
    const int rowA = warp_m + (lane & 7) + ((lane >> 3) & 1) * 8;
    const int chA = (lane >> 4) & 1;
    const int rowB = warp_n + (lane & 7) + ((lane >> 4) & 1) * 8;
    const int chB = (lane >> 3) & 1;
    // trans-path lane addressing
    const int kArow = (lane & 7) + ((lane >> 4) & 1) * 8;
    const int mA8 = ((lane >> 3) & 1) * 8;
    const int kBrow = (lane & 7) + ((lane >> 3) & 1) * 8;
    const int nB8 = ((lane >> 4) & 1) * 8;
    const int lsw = (lane & 7) << 4;

    float acc[4][4][4] = {};

    auto load_stage = [&](int t, int buf) {
        const int k0 = t * KC;
        uint32_t sb = sbase + buf * STAGE;
        #pragma unroll
        for (int a = 0; a < NTA; a++) {
            uint32_t tb = sb + a * ATB;
            #pragma unroll
            for (int pp = 0; pp < OPS; pp++) {
                int id = tid + pp * 256;
                if (!TA) {
                    int row = id / CPR, ch = id % CPR;
                    CP_ASYNC16(tb + row * NAT_RB + ch * 16,
                               gpA[a] + (size_t)row * L + k0 + ch * 8);
                } else {
                    int kr = id >> 4, ch = id & 15;
                    CP_ASYNC16(tb + kr * 256 + ((ch ^ (kr & 7)) << 4),
                               gpA[a] + (size_t)(k0 + kr) * L + ch * 8);
                }
            }
        }
        sb += NTA * ATB;
        #pragma unroll
        for (int a = 0; a < NTB; a++) {
            uint32_t tb = sb + a * BTB;
            #pragma unroll
            for (int pp = 0; pp < OPS; pp++) {
                int id = tid + pp * 256;
                if (!TB) {
                    int row = id / CPR, ch = id % CPR;
                    CP_ASYNC16(tb + row * NAT_RB + ch * 16,
                               gpB[a] + (size_t)row * L + k0 + ch * 8);
                } else {
                    int kr = id >> 4, ch = id & 15;
                    CP_ASYNC16(tb + kr * 256 + ((ch ^ (kr & 7)) << 4),
                               gpB[a] + (size_t)(k0 + kr) * L + ch * 8);
                }
            }
        }
    };

    load_stage(0, 0);
    CP_COMMIT();

    for (int t = 0; t < ktiles; t++) {
        CP_WAIT0();          // stage t resident
        __syncthreads();     // all warps: stage t visible AND done reading buf (t+1)&1
        if (t + 1 < ktiles) { load_stage(t + 1, (t + 1) & 1); CP_COMMIT(); }

        const uint32_t sb = sbase + (t & 1) * STAGE;
        const uint32_t sbB = sb + NTA * ATB;
        #pragma unroll
        for (int ks = 0; ks < KSN; ks++) {
            uint32_t Bf[NTB][8];
            #pragma unroll
            for (int tm = 0; tm < NTB; tm++)
                #pragma unroll
                for (int g2 = 0; g2 < 2; g2++) {
                    if (!TB) {
                        uint32_t a = sbB + tm * BTB + (rowB + g2 * 16) * NAT_RB
                                   + chB * 16 + ks * 32;
                        LDSM4(Bf[tm][g2 * 4 + 0], Bf[tm][g2 * 4 + 1],
                              Bf[tm][g2 * 4 + 2], Bf[tm][g2 * 4 + 3], a);
                    } else {
                        int n_off = warp_n + g2 * 16 + nB8;
                        int kr = ks * 16 + kBrow;
                        uint32_t a = sbB + tm * BTB + kr * 256
                                   + (((n_off >> 3) << 4) ^ lsw);
                        LDSM4T(Bf[tm][g2 * 4 + 0], Bf[tm][g2 * 4 + 1],
                               Bf[tm][g2 * 4 + 2], Bf[tm][g2 * 4 + 3], a);
                    }
                }
            uint32_t Af[16];
            #pragma unroll
            for (int p = 0; p < NP; p++) {
                const int pa = (NP == 3) ? PA3[p] : 0;
                const int pb = (NP == 3) ? PB3[p] : 0;
                const int pap = (p == 0) ? -1 : ((NP == 3) ? PA3[p - 1] : 0);
                if (pa != pap) {
                    #pragma unroll
                    for (int f = 0; f < 4; f++) {
                        if (!TA) {
                            uint32_t a = sb + pa * ATB + (rowA + f * 16) * NAT_RB
                                       + chA * 16 + ks * 32;
                            LDSM4(Af[f * 4 + 0], Af[f * 4 + 1],
                                  Af[f * 4 + 2], Af[f * 4 + 3], a);
                        } else {
                            int m_off = warp_m + f * 16 + mA8;
                            int kr = ks * 16 + kArow;
                            uint32_t a = sb + pa * ATB + kr * 256
                                       + (((m_off >> 3) << 4) ^ lsw);
                            LDSM4T(Af[f * 4 + 0], Af[f * 4 + 1],
                                   Af[f * 4 + 2], Af[f * 4 + 3], a);
                        }
                    }
                }
                #pragma unroll
                for (int f = 0; f < 4; f++)
                    #pragma unroll
                    for (int g = 0; g < 4; g++) {
                        uint32_t b0 = Bf[pb][(g >> 1) * 4 + (g & 1) * 2];
                        uint32_t b1 = Bf[pb][(g >> 1) * 4 + (g & 1) * 2 + 1];
                        mma16816(acc[f][g][0], acc[f][g][1], acc[f][g][2], acc[f][g][3],
                                 Af[f * 4], Af[f * 4 + 1], Af[f * 4 + 2], Af[f * 4 + 3],
                                 b0, b1);
                    }
            }
        }
    }

    float* Ob = Out + boff;
    #pragma unroll
    for (int f = 0; f < 4; f++)
        #pragma unroll
        for (int g = 0; g < 4; g++) {
            int row = m0 + warp_m + f * 16 + (lane >> 2);
            int col = n0 + warp_n + g * 8 + (lane & 3) * 2;
            *(float2*)(Ob + (size_t)row * L + col) = make_float2(acc[f][g][0], acc[f][g][1]);
            *(float2*)(Ob + (size_t)(row + 8) * L + col) = make_float2(acc[f][g][2], acc[f][g][3]);
            if (EPI16) {
                __half* Oh = Out16 + boff;
                *(__half2*)(Oh + (size_t)row * L + col) =
                    __floats2half2_rn(acc[f][g][0], acc[f][g][1]);
                *(__half2*)(Oh + (size_t)(row + 8) * L + col) =
                    __floats2half2_rn(acc[f][g][2], acc[f][g][3]);
            }
        }
}

// ---------------------------------------------------------------------------
extern "C" void kernel_launch(void* const* d_in, const int* in_sizes, int n_in,
                              void* d_out, int out_size) {
    const float* q = (const float*)d_in[0];
    const float* dmat = (const float*)d_in[1];
    const int* qlen = (const int*)d_in[2];
    const int* dlen = (const int*)d_in[3];

    float* out = (float*)d_out;
    const size_t ten = (size_t)BATCH * L * HD;
    float* out_cd = out;
    float* out_sq = out + ten;
    float* out_sd = out + 2 * ten;

    void *pA, *pq0, *pq1, *pd0, *pd1, *ps, *pwr, *pwc;
    cudaGetSymbolAddress(&pA, g_A);
    cudaGetSymbolAddress(&pq0, g_q0); cudaGetSymbolAddress(&pq1, g_q1);
    cudaGetSymbolAddress(&pd0, g_d0); cudaGetSymbolAddress(&pd1, g_d1);
    cudaGetSymbolAddress(&ps, g_s);
    cudaGetSymbolAddress(&pwr, g_wr); cudaGetSymbolAddress(&pwc, g_wc);

    // K1: Kc=32, 4 natural tiles of 128*80B = 10240 -> stage 40960, x2 = 81920
    const int SMEM_K1 = 2 * 4 * (128 * 80);
    // K3: Kc=64, natural(wr) 18432 + trans(d) 16384 -> x2 = 69632
    const int SMEM_K3 = 2 * (128 * 144 + 64 * 256);
    // K4/5: Kc=64, 2 trans tiles -> x2 = 65536
    const int SMEM_K45 = 2 * 2 * (64 * 256);
    cudaFuncSetAttribute(k_mma<2, 2, 3, 0, 0, 0, 32>,
                         cudaFuncAttributeMaxDynamicSharedMemorySize, SMEM_K1);
    cudaFuncSetAttribute(k_mma<1, 1, 1, 0, 1, 1, 64>,
                         cudaFuncAttributeMaxDynamicSharedMemorySize, SMEM_K3);
    cudaFuncSetAttribute(k_mma<1, 1, 1, 1, 1, 0, 64>,
                         cudaFuncAttributeMaxDynamicSharedMemorySize, SMEM_K45);

    dim3 gg(HD / 128, L / 128, BATCH);
    int nsplit = (int)(NEL / 4 / 256);

    // 1) 2-way fp16 splits (hi terms double as natural fp16 q/d for trans loads)
    k_split2h<<<nsplit, 256>>>((const float4*)q, (uint2*)pq0, (uint2*)pq1);
    k_split2h<<<nsplit, 256>>>((const float4*)dmat, (uint2*)pd0, (uint2*)pd1);

    // 2) K1: A = q @ d^T  (fp32-grade via 3 fp16 product terms; 2 CTAs/SM)
    k_mma<2, 2, 3, 0, 0, 0, 32><<<gg, 256, SMEM_K1>>>(
        (const __half*)pq0, (const __half*)pq1,
        (const __half*)pd0, (const __half*)pd1,
        nullptr, L, (float*)pA, nullptr);

    // 3) softmax stats
    k_row_stats<<<dim3(L / 8, BATCH), 256>>>(dlen);
    k_col_stats<<<dim3(L / 256, BATCH), 256>>>(qlen);

    // 4) fused streaming weights (wr + wc, both natural fp16)
    k_weights<<<dim3(L, BATCH), 256>>>(qlen, dlen);

    // 5) K3: sq^T = Wr @ d^T  (A natural, B=d trans; epilogue also emits fp16 sq^T)
    k_mma<1, 1, 1, 0, 1, 1, 64><<<gg, 256, SMEM_K3>>>(
        (const __half*)pwr, nullptr, (const __half*)pd0, nullptr,
        dlen, 0, out_sq, (__half*)ps);

    // 6) K4: sd^T = Wc @ q^T  (A=wc trans, B=q trans)
    k_mma<1, 1, 1, 1, 1, 0, 64><<<gg, 256, SMEM_K45>>>(
        (const __half*)pwc, nullptr, (const __half*)pq0, nullptr,
        qlen, 0, out_sd, nullptr);

    // 7) K5: cd^T = Wc @ sq^T (A=wc trans, B=sq^T fp16 trans)
    k_mma<1, 1, 1, 1, 1, 0, 64><<<gg, 256, SMEM_K45>>>(
        (const __half*)pwc, nullptr, (const __half*)ps, nullptr,
        qlen, 0, out_cd, nullptr);
}

// round 9
// speedup vs baseline: 6.8839x; 1.1152x over previous
#include <cuda_runtime.h>
#include <cuda_fp16.h>
#include <cstdint>

#define BATCH 32
#define L 1024
#define HD 1024

// ---------------------------------------------------------------------------
// Scratch (__device__ globals; no runtime allocation)
// ---------------------------------------------------------------------------
__device__ float g_A[(size_t)BATCH * L * L];   // raw logits, 128 MB
__device__ float g_rmax[BATCH * L];
__device__ float g_rinv[BATCH * L];
__device__ float g_cmax[BATCH * L];
__device__ float g_cinv[BATCH * L];

#define NEL ((size_t)BATCH * L * HD)
__device__ __half g_q0[NEL], g_q1[NEL];   // q 2-way fp16 split (natural [q][h])
__device__ __half g_d0[NEL], g_d1[NEL];   // d 2-way fp16 split (natural [dp][h])
__device__ __half g_s[NEL];               // sq^T fp16 copy (natural [q][h])
__device__ __half g_wr[NEL];              // row-softmax weights [q][dp], fp16
__device__ __half g_wc[NEL];              // col-softmax weights [q][dp] NATURAL, fp16

// ---------------------------------------------------------------------------
// Helpers
// ---------------------------------------------------------------------------
__device__ __forceinline__ uint32_t smem_u32(const void* p) {
    uint32_t a;
    asm("{ .reg .u64 t; cvta.to.shared.u64 t, %1; cvt.u32.u64 %0, t; }" : "=r"(a) : "l"(p));
    return a;
}

#define LDSM4(R0, R1, R2, R3, addr)                                             \
    asm volatile("ldmatrix.sync.aligned.m8n8.x4.shared.b16 {%0,%1,%2,%3}, [%4];" \
                 : "=r"(R0), "=r"(R1), "=r"(R2), "=r"(R3) : "r"(addr))
#define LDSM4T(R0, R1, R2, R3, addr)                                                  \
    asm volatile("ldmatrix.sync.aligned.m8n8.x4.trans.shared.b16 {%0,%1,%2,%3}, [%4];" \
                 : "=r"(R0), "=r"(R1), "=r"(R2), "=r"(R3) : "r"(addr))

#define CP_ASYNC16(saddr, gaddr) \
    asm volatile("cp.async.cg.shared.global [%0], [%1], 16;" :: "r"(saddr), "l"(gaddr))
#define CP_COMMIT() asm volatile("cp.async.commit_group;" ::: "memory")
#define CP_WAIT0()  asm volatile("cp.async.wait_group 0;" ::: "memory")

__device__ __forceinline__ void mma16816(float& c0, float& c1, float& c2, float& c3,
                                         uint32_t a0, uint32_t a1, uint32_t a2, uint32_t a3,
                                         uint32_t b0, uint32_t b1) {
    asm volatile(
        "mma.sync.aligned.m16n8k16.row.col.f32.f16.f16.f32 "
        "{%0,%1,%2,%3}, {%4,%5,%6,%7}, {%8,%9}, {%0,%1,%2,%3};"
        : "+f"(c0), "+f"(c1), "+f"(c2), "+f"(c3)
        : "r"(a0), "r"(a1), "r"(a2), "r"(a3), "r"(b0), "r"(b1));
}

// ---------------------------------------------------------------------------
// Conversion kernels
// ---------------------------------------------------------------------------
union HU4 { __half h[4]; uint2 u; };

// fp32 -> 2-way fp16 split, natural layout
__global__ __launch_bounds__(256) void k_split2h(const float4* __restrict__ x,
                                                 uint2* __restrict__ o0,
                                                 uint2* __restrict__ o1) {
    size_t i = (size_t)blockIdx.x * 256 + threadIdx.x;
    float4 v = x[i];
    float xs[4] = {v.x, v.y, v.z, v.w};
    HU4 p0, p1;
    #pragma unroll
    for (int c = 0; c < 4; c++) {
        p0.h[c] = __float2half_rn(xs[c]);
        p1.h[c] = __float2half_rn(xs[c] - __half2float(p0.h[c]));
    }
    o0[i] = p0.u;
    o1[i] = p1.u;
}

// Streaming weight generation (both NATURAL [q][dp], fully coalesced):
//   wr[q][dp] = exp(A - rmax[q]) * rinv[q]    (0 for dp >= dlen)
//   wc[q][dp] = exp(A - cmax[dp]) * cinv[dp]  (0 for q  >= qlen)
__global__ __launch_bounds__(256) void k_weights(const int* __restrict__ qlen,
                                                 const int* __restrict__ dlen) {
    int b = blockIdx.y, qq = blockIdx.x, tid = threadIdx.x;
    int klq = qlen[b], kld = dlen[b];
    float rm = g_rmax[b * L + qq], ri = g_rinv[b * L + qq];
    size_t base = ((size_t)b << 20) + ((size_t)qq << 10);
    float4 v = *(const float4*)(g_A + base + tid * 4);
    float4 cm = *(const float4*)(g_cmax + b * L + tid * 4);
    float4 ci = *(const float4*)(g_cinv + b * L + tid * 4);
    float xs[4] = {v.x, v.y, v.z, v.w};
    float cms[4] = {cm.x, cm.y, cm.z, cm.w};
    float cis[4] = {ci.x, ci.y, ci.z, ci.w};
    HU4 pr, pc;
    bool qv = qq < klq;
    #pragma unroll
    for (int c = 0; c < 4; c++) {
        int dp = tid * 4 + c;
        float wr = (dp < kld) ? __expf(xs[c] - rm) * ri : 0.f;
        float wc = qv ? __expf(xs[c] - cms[c]) * cis[c] : 0.f;
        pr.h[c] = __float2half_rn(wr);
        pc.h[c] = __float2half_rn(wc);
    }
    size_t oi = (base >> 2) + tid;
    ((uint2*)g_wr)[oi] = pr.u;
    ((uint2*)g_wc)[oi] = pc.u;
}

// ---------------------------------------------------------------------------
// Softmax statistics
// ---------------------------------------------------------------------------
__global__ __launch_bounds__(256) void k_row_stats(const int* __restrict__ dlen) {
    int b = blockIdx.y;
    int row = blockIdx.x * 8 + (threadIdx.x >> 5);
    int lane = threadIdx.x & 31;
    int kl = dlen[b];
    const float4* Ar = (const float4*)(g_A + ((size_t)b << 20) + ((size_t)row << 10));
    float v[32];
    #pragma unroll
    for (int i = 0; i < 8; i++) {
        // predicated load: only touch data below d_len (saves ~half the traffic)
        if (lane * 4 + i * 128 < kl) {
            float4 t = Ar[lane + i * 32];
            v[i * 4 + 0] = t.x; v[i * 4 + 1] = t.y; v[i * 4 + 2] = t.z; v[i * 4 + 3] = t.w;
        } else {
            v[i * 4 + 0] = v[i * 4 + 1] = v[i * 4 + 2] = v[i * 4 + 3] = -1e30f;
        }
    }
    float m = -1e30f;
    #pragma unroll
    for (int i = 0; i < 8; i++)
        #pragma unroll
        for (int c = 0; c < 4; c++) {
            int idx = (lane + i * 32) * 4 + c;
            if (idx >= kl) v[i * 4 + c] = -1e30f;
            m = fmaxf(m, v[i * 4 + c]);
        }
    #pragma unroll
    for (int off = 16; off; off >>= 1) m = fmaxf(m, __shfl_xor_sync(~0u, m, off));
    float s = 0.f;
    #pragma unroll
    for (int i = 0; i < 32; i++) s += __expf(v[i] - m);
    #pragma unroll
    for (int off = 16; off; off >>= 1) s += __shfl_xor_sync(~0u, s, off);
    if (lane == 0) {
        g_rmax[b * L + row] = m;
        g_rinv[b * L + row] = 1.f / s;
    }
}

__global__ __launch_bounds__(256) void k_col_stats(const int* __restrict__ qlen) {
    int b = blockIdx.y;
    int col = blockIdx.x * 256 + threadIdx.x;
    int kl = qlen[b];
    const float* Ab = g_A + ((size_t)b << 20) + col;
    float m[4] = {-1e30f, -1e30f, -1e30f, -1e30f}, s[4] = {0.f, 0.f, 0.f, 0.f};
    int q = 0;
    for (; q + 4 <= kl; q += 4) {
        #pragma unroll
        for (int i = 0; i < 4; i++) {
            float v = Ab[(size_t)(q + i) << 10];
            float nm = fmaxf(m[i], v);
            s[i] = s[i] * __expf(m[i] - nm) + __expf(v - nm);
            m[i] = nm;
        }
    }
    for (; q < kl; q++) {
        float v = Ab[(size_t)q << 10];
        float nm = fmaxf(m[0], v);
        s[0] = s[0] * __expf(m[0] - nm) + __expf(v - nm);
        m[0] = nm;
    }
    float M = fmaxf(fmaxf(m[0], m[1]), fmaxf(m[2], m[3]));
    float S = 0.f;
    #pragma unroll
    for (int i = 0; i < 4; i++) S += s[i] * __expf(m[i] - M);
    g_cmax[b * L + col] = M;
    g_cinv[b * L + col] = 1.f / S;
}

// ---------------------------------------------------------------------------
// Split-fp16 HMMA GEMM. Out[m][n] = sum_k A(m,k) * B(n,k).
// TA/TB: 0 = K-major natural -> ldmatrix; 1 = k-row natural -> ldmatrix.trans.
// Block 128x128, warp tile 64x32 (2x4 warps), Kc templated, cp.async x2 buffer.
// SKIP: CTA exits when (m0 >= skq[b] && n0 >= skd[b]) -- the output region is
// never consumed (weights there are 0 and downstream K-loops never reach it).
// ---------------------------------------------------------------------------
template <int NTA, int NTB, int NP, int TA, int TB, int EPI16, int KC, int SKIP>
__global__ __launch_bounds__(256, 2) void k_mma(
    const __half* __restrict__ A0, const __half* __restrict__ A1,
    const __half* __restrict__ B0, const __half* __restrict__ B1,
    const int* klen_arr, int klen_fixed,
    float* __restrict__ Out, __half* __restrict__ Out16,
    const int* __restrict__ skq, const int* __restrict__ skd) {
    extern __shared__ char smem[];
    const uint32_t sbase = smem_u32(smem);
    constexpr int NAT_RB = KC * 2 + 16;          // natural row bytes (pad 16)
    constexpr int NAT_TB = 128 * NAT_RB;
    constexpr int TRN_TB = KC * 256;
    constexpr int ATB = TA ? TRN_TB : NAT_TB;
    constexpr int BTB = TB ? TRN_TB : NAT_TB;
    constexpr int STAGE = NTA * ATB + NTB * BTB;
    constexpr int CPR = KC / 8;                  // 16B chunks per natural row
    constexpr int OPS = KC * 16 / 256;           // cp.async per thread per tile
    constexpr int KSN = KC / 16;                 // k16 steps per chunk

    const int tid = threadIdx.x, lane = tid & 31, wid = tid >> 5;
    const int b = blockIdx.z, m0 = blockIdx.y * 128, n0 = blockIdx.x * 128;

    if (SKIP) {
        if (m0 >= skq[b] && n0 >= skd[b]) return;   // unconsumed A region
    }

    const int kl = klen_arr ? klen_arr[b] : klen_fixed;
    const int ktiles = (kl + KC - 1) / KC;

    const size_t boff = (size_t)b << 20;
    const __half* gpA[NTA];
    const __half* gpB[NTB];
    gpA[0] = A0 + boff + (TA ? (size_t)m0 : (size_t)m0 * L);
    if (NTA == 2) gpA[1] = A1 + boff + (TA ? (size_t)m0 : (size_t)m0 * L);
    gpB[0] = B0 + boff + (TB ? (size_t)n0 : (size_t)n0 * L);
    if (NTB == 2) gpB[1] = B1 + boff + (TB ? (size_t)n0 : (size_t)n0 * L);

    constexpr int PA3[3] = {0, 0, 1}, PB3[3] = {0, 1, 0};

    // warp layout: 2 (m) x 4 (n)
    const int warp_m = (wid >> 2) * 64;
    const int warp_n = (wid & 3) * 32;
    // natural-path lane addressing
    const int rowA = warp_m + (lane & 7) + ((lane >> 3) & 1) * 8;
    const int chA = (lane >> 4) & 1;
    const int rowB = warp_n + (lane & 7) + ((lane >> 4) & 1) * 8;
    const int chB = (lane >> 3) & 1;
    // trans-path lane addressing
    const int kArow = (lane & 7) + ((lane >> 4) & 1) * 8;
    const int mA8 = ((lane >> 3) & 1) * 8;
    const int kBrow = (lane & 7) + ((lane >> 3) & 1) * 8;
    const int nB8 = ((lane >> 4) & 1) * 8;
    const int lsw = (lane & 7) << 4;

    float acc[4][4][4] = {};

    auto load_stage = [&](int t, int buf) {
        const int k0 = t * KC;
        uint32_t sb = sbase + buf * STAGE;
        #pragma unroll
        for (int a = 0; a < NTA; a++) {
            uint32_t tb = sb + a * ATB;
            #pragma unroll
            for (int pp = 0; pp < OPS; pp++) {
                int id = tid + pp * 256;
                if (!TA) {
                    int row = id / CPR, ch = id % CPR;
                    CP_ASYNC16(tb + row * NAT_RB + ch * 16,
                               gpA[a] + (size_t)row * L + k0 + ch * 8);
                } else {
                    int kr = id >> 4, ch = id & 15;
                    CP_ASYNC16(tb + kr * 256 + ((ch ^ (kr & 7)) << 4),
                               gpA[a] + (size_t)(k0 + kr) * L + ch * 8);
                }
            }
        }
        sb += NTA * ATB;
        #pragma unroll
        for (int a = 0; a < NTB; a++) {
            uint32_t tb = sb + a * BTB;
            #pragma unroll
            for (int pp = 0; pp < OPS; pp++) {
                int id = tid + pp * 256;
                if (!TB) {
                    int row = id / CPR, ch = id % CPR;
                    CP_ASYNC16(tb + row * NAT_RB + ch * 16,
                               gpB[a] + (size_t)row * L + k0 + ch * 8);
                } else {
                    int kr = id >> 4, ch = id & 15;
                    CP_ASYNC16(tb + kr * 256 + ((ch ^ (kr & 7)) << 4),
                               gpB[a] + (size_t)(k0 + kr) * L + ch * 8);
                }
            }
        }
    };

    load_stage(0, 0);
    CP_COMMIT();

    for (int t = 0; t < ktiles; t++) {
        CP_WAIT0();          // stage t resident
        __syncthreads();     // stage t visible AND all warps done with buf (t+1)&1
        if (t + 1 < ktiles) { load_stage(t + 1, (t + 1) & 1); CP_COMMIT(); }

        const uint32_t sb = sbase + (t & 1) * STAGE;
        const uint32_t sbB = sb + NTA * ATB;
        #pragma unroll
        for (int ks = 0; ks < KSN; ks++) {
            uint32_t Bf[NTB][8];
            #pragma unroll
            for (int tm = 0; tm < NTB; tm++)
                #pragma unroll
                for (int g2 = 0; g2 < 2; g2++) {
                    if (!TB) {
                        uint32_t a = sbB + tm * BTB + (rowB + g2 * 16) * NAT_RB
                                   + chB * 16 + ks * 32;
                        LDSM4(Bf[tm][g2 * 4 + 0], Bf[tm][g2 * 4 + 1],
                              Bf[tm][g2 * 4 + 2], Bf[tm][g2 * 4 + 3], a);
                    } else {
                        int n_off = warp_n + g2 * 16 + nB8;
                        int kr = ks * 16 + kBrow;
                        uint32_t a = sbB + tm * BTB + kr * 256
                                   + (((n_off >> 3) << 4) ^ lsw);
                        LDSM4T(Bf[tm][g2 * 4 + 0], Bf[tm][g2 * 4 + 1],
                               Bf[tm][g2 * 4 + 2], Bf[tm][g2 * 4 + 3], a);
                    }
                }
            uint32_t Af[16];
            #pragma unroll
            for (int p = 0; p < NP; p++) {
                const int pa = (NP == 3) ? PA3[p] : 0;
                const int pb = (NP == 3) ? PB3[p] : 0;
                const int pap = (p == 0) ? -1 : ((NP == 3) ? PA3[p - 1] : 0);
                if (pa != pap) {
                    #pragma unroll
                    for (int f = 0; f < 4; f++) {
                        if (!TA) {
                            uint32_t a = sb + pa * ATB + (rowA + f * 16) * NAT_RB
                                       + chA * 16 + ks * 32;
                            LDSM4(Af[f * 4 + 0], Af[f * 4 + 1],
                                  Af[f * 4 + 2], Af[f * 4 + 3], a);
                        } else {
                            int m_off = warp_m + f * 16 + mA8;
                            int kr = ks * 16 + kArow;
                            uint32_t a = sb + pa * ATB + kr * 256
                                       + (((m_off >> 3) << 4) ^ lsw);
                            LDSM4T(Af[f * 4 + 0], Af[f * 4 + 1],
                                   Af[f * 4 + 2], Af[f * 4 + 3], a);
                        }
                    }
                }
                #pragma unroll
                for (int f = 0; f < 4; f++)
                    #pragma unroll
                    for (int g = 0; g < 4; g++) {
                        uint32_t b0 = Bf[pb][(g >> 1) * 4 + (g & 1) * 2];
                        uint32_t b1 = Bf[pb][(g >> 1) * 4 + (g & 1) * 2 + 1];
                        mma16816(acc[f][g][0], acc[f][g][1], acc[f][g][2], acc[f][g][3],
                                 Af[f * 4], Af[f * 4 + 1], Af[f * 4 + 2], Af[f * 4 + 3],
                                 b0, b1);
                    }
            }
        }
    }

    float* Ob = Out + boff;
    #pragma unroll
    for (int f = 0; f < 4; f++)
        #pragma unroll
        for (int g = 0; g < 4; g++) {
            int row = m0 + warp_m + f * 16 + (lane >> 2);
            int col = n0 + warp_n + g * 8 + (lane & 3) * 2;
            *(float2*)(Ob + (size_t)row * L + col) = make_float2(acc[f][g][0], acc[f][g][1]);
            *(float2*)(Ob + (size_t)(row + 8) * L + col) = make_float2(acc[f][g][2], acc[f][g][3]);
            if (EPI16) {
                __half* Oh = Out16 + boff;
                *(__half2*)(Oh + (size_t)row * L + col) =
                    __floats2half2_rn(acc[f][g][0], acc[f][g][1]);
                *(__half2*)(Oh + (size_t)(row + 8) * L + col) =
                    __floats2half2_rn(acc[f][g][2], acc[f][g][3]);
            }
        }
}

// ---------------------------------------------------------------------------
extern "C" void kernel_launch(void* const* d_in, const int* in_sizes, int n_in,
                              void* d_out, int out_size) {
    const float* q = (const float*)d_in[0];
    const float* dmat = (const float*)d_in[1];
    const int* qlen = (const int*)d_in[2];
    const int* dlen = (const int*)d_in[3];

    float* out = (float*)d_out;
    const size_t ten = (size_t)BATCH * L * HD;
    float* out_cd = out;
    float* out_sq = out + ten;
    float* out_sd = out + 2 * ten;

    void *pA, *pq0, *pq1, *pd0, *pd1, *ps, *pwr, *pwc;
    cudaGetSymbolAddress(&pA, g_A);
    cudaGetSymbolAddress(&pq0, g_q0); cudaGetSymbolAddress(&pq1, g_q1);
    cudaGetSymbolAddress(&pd0, g_d0); cudaGetSymbolAddress(&pd1, g_d1);
    cudaGetSymbolAddress(&ps, g_s);
    cudaGetSymbolAddress(&pwr, g_wr); cudaGetSymbolAddress(&pwc, g_wc);

    // K1: Kc=32, 4 natural tiles of 128*80B = 10240 -> stage 40960, x2 = 81920
    const int SMEM_K1 = 2 * 4 * (128 * 80);
    // K3: Kc=64, natural(wr) 18432 + trans(d) 16384 -> x2 = 69632
    const int SMEM_K3 = 2 * (128 * 144 + 64 * 256);
    // K4/5: Kc=64, 2 trans tiles -> x2 = 65536
    const int SMEM_K45 = 2 * 2 * (64 * 256);
    cudaFuncSetAttribute(k_mma<2, 2, 3, 0, 0, 0, 32, 1>,
                         cudaFuncAttributeMaxDynamicSharedMemorySize, SMEM_K1);
    cudaFuncSetAttribute(k_mma<1, 1, 1, 0, 1, 1, 64, 0>,
                         cudaFuncAttributeMaxDynamicSharedMemorySize, SMEM_K3);
    cudaFuncSetAttribute(k_mma<1, 1, 1, 1, 1, 0, 64, 0>,
                         cudaFuncAttributeMaxDynamicSharedMemorySize, SMEM_K45);

    dim3 gg(HD / 128, L / 128, BATCH);
    int nsplit = (int)(NEL / 4 / 256);

    // 1) 2-way fp16 splits (hi terms double as natural fp16 q/d for trans loads)
    k_split2h<<<nsplit, 256>>>((const float4*)q, (uint2*)pq0, (uint2*)pq1);
    k_split2h<<<nsplit, 256>>>((const float4*)dmat, (uint2*)pd0, (uint2*)pd1);

    // 2) K1: A = q @ d^T  (3 fp16 product terms; skip unconsumed masked tiles)
    k_mma<2, 2, 3, 0, 0, 0, 32, 1><<<gg, 256, SMEM_K1>>>(
        (const __half*)pq0, (const __half*)pq1,
        (const __half*)pd0, (const __half*)pd1,
        nullptr, L, (float*)pA, nullptr, qlen, dlen);

    // 3) softmax stats
    k_row_stats<<<dim3(L / 8, BATCH), 256>>>(dlen);
    k_col_stats<<<dim3(L / 256, BATCH), 256>>>(qlen);

    // 4) fused streaming weights (wr + wc, both natural fp16)
    k_weights<<<dim3(L, BATCH), 256>>>(qlen, dlen);

    // 5) K3: sq^T = Wr @ d^T  (A natural, B=d trans; epilogue also emits fp16 sq^T)
    k_mma<1, 1, 1, 0, 1, 1, 64, 0><<<gg, 256, SMEM_K3>>>(
        (const __half*)pwr, nullptr, (const __half*)pd0, nullptr,
        dlen, 0, out_sq, (__half*)ps, nullptr, nullptr);

    // 6) K4: sd^T = Wc @ q^T  (A=wc trans, B=q trans)
    k_mma<1, 1, 1, 1, 1, 0, 64, 0><<<gg, 256, SMEM_K45>>>(
        (const __half*)pwc, nullptr, (const __half*)pq0, nullptr,
        qlen, 0, out_sd, nullptr, nullptr, nullptr);

    // 7) K5: cd^T = Wc @ sq^T (A=wc trans, B=sq^T fp16 trans)
    k_mma<1, 1, 1, 1, 1, 0, 64, 0><<<gg, 256, SMEM_K45>>>(
        (const __half*)pwc, nullptr, (const __half*)ps, nullptr,
        qlen, 0, out_cd, nullptr, nullptr, nullptr);
}